// round 5
// baseline (speedup 1.0000x reference)
#include <cuda_runtime.h>
#include <cuda_bf16.h>
#include <cstdint>

#define MAXN 100000
#define MAXE 1600000

// ---------------- device scratch ----------------
__device__ __align__(16) float g_xl[(size_t)MAXN * 128];
__device__ __align__(16) float g_xr[(size_t)MAXN * 128];
__device__ float g_xld[MAXN * 2];
__device__ float g_xrd[MAXN * 2];
__device__ float g_sdec[MAXN];
__device__ float g_accdec[MAXN * 2];
__device__ int   g_cnt[MAXN];
__device__ int   g_off[MAXN + 1];
__device__ int   g_cur[MAXN];
__device__ int   g_csr[2 * MAXE];
__device__ int   g_dec[MAXN];
__device__ float g_gate[MAXN];
__device__ int   g_part[256];
__device__ int   g_is64;
// W^T bf16 hi/lo, layout [n][k] (k contiguous): [Wl_hi, Wl_lo, Wr_hi, Wr_lo]
__device__ __align__(16) __nv_bfloat16 g_wtb[4][16384];

// ---------------- helpers ----------------
__device__ __forceinline__ float lrelu(float v) { return v > 0.f ? v : 0.2f * v; }

__device__ __forceinline__ float warp_sum(float v) {
#pragma unroll
    for (int o = 16; o; o >>= 1) v += __shfl_xor_sync(0xffffffffu, v, o);
    return v;
}

__device__ __forceinline__ uint32_t smem_u32(const void* p) {
    uint32_t a;
    asm("{ .reg .u64 t; cvta.to.shared.u64 t, %1; cvt.u32.u64 %0, t; }" : "=r"(a) : "l"(p));
    return a;
}

__device__ __forceinline__ void ldsm_x4(uint32_t* r, uint32_t addr) {
    asm volatile("ldmatrix.sync.aligned.m8n8.x4.shared.b16 {%0,%1,%2,%3}, [%4];"
                 : "=r"(r[0]), "=r"(r[1]), "=r"(r[2]), "=r"(r[3]) : "r"(addr));
}
__device__ __forceinline__ void ldsm_x2(uint32_t* r, uint32_t addr) {
    asm volatile("ldmatrix.sync.aligned.m8n8.x2.shared.b16 {%0,%1}, [%2];"
                 : "=r"(r[0]), "=r"(r[1]) : "r"(addr));
}
__device__ __forceinline__ void mma16816(float* d, const uint32_t* a, const uint32_t* b) {
    asm volatile(
        "mma.sync.aligned.m16n8k16.row.col.f32.bf16.bf16.f32 "
        "{%0,%1,%2,%3}, {%4,%5,%6,%7}, {%8,%9}, {%0,%1,%2,%3};"
        : "+f"(d[0]), "+f"(d[1]), "+f"(d[2]), "+f"(d[3])
        : "r"(a[0]), "r"(a[1]), "r"(a[2]), "r"(a[3]), "r"(b[0]), "r"(b[1]));
}

// ---------------- dtype detection ----------------
__global__ void k_detect(const int* __restrict__ e) {
    int t = threadIdx.x;
    int nz = e[2 * t + 1] | e[2 * (t + 32) + 1] | e[2 * (t + 64) + 1] | e[2 * (t + 96) + 1];
    unsigned m = __ballot_sync(0xffffffffu, nz != 0);
    if (t == 0) g_is64 = (m == 0) ? 1 : 0;
}

// ---------------- zero scratch ----------------
__global__ void k_zero(int n) {
    int i = blockIdx.x * blockDim.x + threadIdx.x;
    if (i < 2 * n) {
        g_accdec[i] = 0.f;
        if (i < n) { g_sdec[i] = 0.f; g_cnt[i] = 0; }
    }
}

// ---------------- W^T bf16 hi/lo prep: g_wtb[.][n*128+k] ----------------
__global__ void k_prepW(const float* __restrict__ wl, const float* __restrict__ wr) {
    int i = blockIdx.x * blockDim.x + threadIdx.x;  // 0..32767
    if (i >= 32768) return;
    int m = i >> 14;
    int rem = i & 16383;
    int k = rem >> 7, nn = rem & 127;   // coalesced read over nn
    float w = (m ? wr : wl)[k * 128 + nn];
    __nv_bfloat16 hi = __float2bfloat16(w);
    __nv_bfloat16 lo = __float2bfloat16(w - __bfloat162float(hi));
    g_wtb[2 * m + 0][nn * 128 + k] = hi;
    g_wtb[2 * m + 1][nn * 128 + k] = lo;
}

// ---------------- fused bf16 split-K mma GEMM: xl AND xr in one pass ----------------
// Output is 128 rows x 256 cols (xl cols 0..127 from Wl, xr cols from Wr).
// 3-term: Ah*Bh + Ah*Bl + Al*Bh.  Slabs of K=64, padded rows of 72 bf16.
#define SLAB_ROW 72
#define SLAB_BYTES 18432                    // 128*72*2
#define SM_A_HI 0
#define SM_A_LO SLAB_BYTES
#define SM_B    (2 * SLAB_BYTES)            // 4 slabs: [out][ver]
#define SM_GEMM_TOTAL (6 * SLAB_BYTES)      // 110592

__global__ __launch_bounds__(512, 1) void k_mma2(const float* __restrict__ X,
                                                 const float* __restrict__ bl,
                                                 const float* __restrict__ br, int n) {
    extern __shared__ __align__(16) unsigned char sm[];
    __nv_bfloat16* Ah = (__nv_bfloat16*)(sm + SM_A_HI);
    __nv_bfloat16* Al = (__nv_bfloat16*)(sm + SM_A_LO);

    const int tid = threadIdx.x;
    const int w = tid >> 5;
    const int lane = tid & 31;
    const int out = w >> 3;           // 0 -> xl, 1 -> xr
    const int wq = w & 7;
    const int wm = wq & 3;            // m quarter (32 rows)
    const int wcol = (wq >> 2) * 64;  // n half (64 cols)
    const int mBase = blockIdx.x * 128;

    __nv_bfloat16* Bh = (__nv_bfloat16*)(sm + SM_B + out * 2 * SLAB_BYTES);
    __nv_bfloat16* Bl = (__nv_bfloat16*)(sm + SM_B + out * 2 * SLAB_BYTES + SLAB_BYTES);

    float acc[2][8][4];
#pragma unroll
    for (int a = 0; a < 2; a++)
#pragma unroll
        for (int b = 0; b < 8; b++)
#pragma unroll
            for (int c = 0; c < 4; c++) acc[a][b][c] = 0.f;

#pragma unroll
    for (int slab = 0; slab < 2; slab++) {
        const int k0 = slab * 64;
        // ---- A slab: convert 128 rows x 64 k of X into bf16 hi/lo (once!) ----
#pragma unroll
        for (int it = 0; it < 4; it++) {
            int idx = tid + it * 512;     // 0..2047 = 128 rows x 16 float4
            int row = idx >> 4;
            int q = idx & 15;
            float4 v = make_float4(0.f, 0.f, 0.f, 0.f);
            int gr = mBase + row;
            if (gr < n) v = __ldg((const float4*)(X + (size_t)gr * 128 + k0) + q);
            __nv_bfloat162 h01 = __floats2bfloat162_rn(v.x, v.y);
            __nv_bfloat162 h23 = __floats2bfloat162_rn(v.z, v.w);
            float2 f01 = __bfloat1622float2(h01);
            float2 f23 = __bfloat1622float2(h23);
            __nv_bfloat162 l01 = __floats2bfloat162_rn(v.x - f01.x, v.y - f01.y);
            __nv_bfloat162 l23 = __floats2bfloat162_rn(v.z - f23.x, v.w - f23.y);
            uint2 hw, lw;
            hw.x = *(uint32_t*)&h01; hw.y = *(uint32_t*)&h23;
            lw.x = *(uint32_t*)&l01; lw.y = *(uint32_t*)&l23;
            *(uint2*)&Ah[row * SLAB_ROW + q * 4] = hw;
            *(uint2*)&Al[row * SLAB_ROW + q * 4] = lw;
        }
        // ---- B slabs: linear copies from pre-transposed g_wtb (4 sub-slabs) ----
#pragma unroll
        for (int it = 0; it < 8; it++) {
            int idx = tid + it * 512;     // 0..4095: m(2) x ver(2) x 128 rows x 8 float4
            int m = idx >> 11;
            int ver = (idx >> 10) & 1;
            int r = (idx >> 3) & 127;
            int j = idx & 7;
            const float4* src = (const float4*)(g_wtb[2 * m + ver] + r * 128 + k0);
            float4 val = __ldg(src + j);
            __nv_bfloat16* dst = (__nv_bfloat16*)(sm + SM_B + (m * 2 + ver) * SLAB_BYTES);
            *(float4*)(dst + r * SLAB_ROW + j * 8) = val;
        }
        __syncthreads();

        // ---- compute: 4 k16 blocks ----
#pragma unroll
        for (int kb = 0; kb < 4; kb++) {
            uint32_t afh[2][4], afl[2][4];
#pragma unroll
            for (int mb = 0; mb < 2; mb++) {
                int row = wm * 32 + mb * 16 + (lane & 7) + ((lane & 8) ? 8 : 0);
                int colb = kb * 32 + ((lane & 16) ? 16 : 0);
                ldsm_x4(afh[mb], smem_u32(&Ah[row * SLAB_ROW]) + colb);
                ldsm_x4(afl[mb], smem_u32(&Al[row * SLAB_ROW]) + colb);
            }
#pragma unroll
            for (int nb = 0; nb < 8; nb++) {
                int nrow = wcol + nb * 8 + (lane & 7);
                int colb = kb * 32 + ((lane & 8) ? 16 : 0);
                uint32_t bh[2], blr[2];
                ldsm_x2(bh, smem_u32(&Bh[nrow * SLAB_ROW]) + colb);
                ldsm_x2(blr, smem_u32(&Bl[nrow * SLAB_ROW]) + colb);
#pragma unroll
                for (int mb = 0; mb < 2; mb++) {
                    mma16816(acc[mb][nb], afh[mb], bh);
                    mma16816(acc[mb][nb], afh[mb], blr);
                    mma16816(acc[mb][nb], afl[mb], bh);
                }
            }
        }
        __syncthreads();
    }

    // ---- epilogue ----
    float* dst = out ? g_xr : g_xl;
    const float* bias = out ? br : bl;
    int g = lane >> 2, tg = lane & 3;
#pragma unroll
    for (int mb = 0; mb < 2; mb++) {
#pragma unroll
        for (int nb = 0; nb < 8; nb++) {
            int col = wcol + nb * 8 + 2 * tg;
            float2 bv = __ldg((const float2*)(bias + col));
            int row0 = mBase + wm * 32 + mb * 16 + g;
            if (row0 < n) {
                float2 o = make_float2(acc[mb][nb][0] + bv.x, acc[mb][nb][1] + bv.y);
                *(float2*)(dst + (size_t)row0 * 128 + col) = o;
            }
            int row1 = row0 + 8;
            if (row1 < n) {
                float2 o = make_float2(acc[mb][nb][2] + bv.x, acc[mb][nb][3] + bv.y);
                *(float2*)(dst + (size_t)row1 * 128 + col) = o;
            }
        }
    }
}

// ---------------- decision projections (exact fp32) ----------------
__global__ void k_gemmd(const float* __restrict__ x,
                        const float* __restrict__ wl, const float* __restrict__ wr,
                        const float* __restrict__ bl, const float* __restrict__ br, int n) {
    int w = (blockIdx.x * blockDim.x + threadIdx.x) >> 5;
    if (w >= n) return;
    int lane = threadIdx.x & 31;
    float4 xv = __ldg((const float4*)(x + (size_t)w * 128) + lane);
    float xs[4] = {xv.x, xv.y, xv.z, xv.w};
    const float2* WL = (const float2*)wl;
    const float2* WR = (const float2*)wr;
    float pl0 = 0.f, pl1 = 0.f, pr0 = 0.f, pr1 = 0.f;
#pragma unroll
    for (int j = 0; j < 4; j++) {
        float2 a = __ldg(&WL[lane * 4 + j]);
        float2 b = __ldg(&WR[lane * 4 + j]);
        pl0 += xs[j] * a.x; pl1 += xs[j] * a.y;
        pr0 += xs[j] * b.x; pr1 += xs[j] * b.y;
    }
    pl0 = warp_sum(pl0); pl1 = warp_sum(pl1);
    pr0 = warp_sum(pr0); pr1 = warp_sum(pr1);
    if (lane == 0) {
        g_xld[2 * w]     = pl0 + __ldg(&bl[0]);
        g_xld[2 * w + 1] = pl1 + __ldg(&bl[1]);
        g_xrd[2 * w]     = pr0 + __ldg(&br[0]);
        g_xrd[2 * w + 1] = pr1 + __ldg(&br[1]);
    }
}

// ---------------- decision edge pass (no-max softmax, atomics) ----------------
__global__ void k_dec_edges(const int* __restrict__ e, const float* __restrict__ attd, int E) {
    int i = blockIdx.x * blockDim.x + threadIdx.x;
    if (i >= E) return;
    int is64 = g_is64;
    int s = is64 ? e[2 * i] : e[i];
    int d = is64 ? e[2 * (E + i)] : e[E + i];
    float xl0 = g_xld[2 * s], xl1 = g_xld[2 * s + 1];
    float xr0 = g_xrd[2 * d], xr1 = g_xrd[2 * d + 1];
    float a0 = __ldg(&attd[0]), a1 = __ldg(&attd[1]);
    float ee = a0 * lrelu(xl0 + xr0) + a1 * lrelu(xl1 + xr1);
    float w = expf(fminf(ee, 75.f));
    atomicAdd(&g_sdec[d], w);
    atomicAdd(&g_accdec[2 * d], w * xl0);
    atomicAdd(&g_accdec[2 * d + 1], w * xl1);
}

// ---------------- decision finalize: self loop + logits + hard gumbel ----------------
__global__ void k_dec_final(const float* __restrict__ gum, const float* __restrict__ attd,
                            const float* __restrict__ biasd, int n) {
    int i = blockIdx.x * blockDim.x + threadIdx.x;
    if (i >= n) return;
    float xl0 = g_xld[2 * i], xl1 = g_xld[2 * i + 1];
    float xr0 = g_xrd[2 * i], xr1 = g_xrd[2 * i + 1];
    float a0 = __ldg(&attd[0]), a1 = __ldg(&attd[1]);
    float ee = a0 * lrelu(xl0 + xr0) + a1 * lrelu(xl1 + xr1);
    float w = expf(fminf(ee, 75.f));
    float s = g_sdec[i] + w;
    float A0 = g_accdec[2 * i] + w * xl0;
    float A1 = g_accdec[2 * i + 1] + w * xl1;
    float inv = 1.f / (s + 1e-16f);
    float l0 = A0 * inv + __ldg(&biasd[0]);
    float l1 = A1 * inv + __ldg(&biasd[1]);
    float z0 = (l0 + gum[2 * i]) * 2.0f;       // /tau, tau=0.5
    float z1 = (l1 + gum[2 * i + 1]) * 2.0f;
    int c = (z0 >= z1) ? 0 : 1;
    float du = (c == 0) ? (z1 - z0) : (z0 - z1);
    float p = 1.f / (1.f + expf(du));
    volatile float t = 1.0f + p;
    g_dec[i] = c;
    g_gate[i] = t - p;
}

// ---------------- decision-filtered hist (both sets, one launch) ----------------
__global__ void k_hist(const int* __restrict__ e0, const int* __restrict__ e1,
                       int E, int eBlocks) {
    int set = (blockIdx.x >= eBlocks) ? 1 : 0;
    int i = (blockIdx.x - set * eBlocks) * blockDim.x + threadIdx.x;
    if (i >= E) return;
    const int* e = set ? e1 : e0;
    int d = g_is64 ? e[2 * (E + i)] : e[E + i];
    if (g_dec[d] == set) atomicAdd(&g_cnt[d], 1);
}

// ---------------- scans (single combined array) ----------------
__global__ void k_scan1(int n) {
    int i = blockIdx.x * 512 + threadIdx.x;
    __shared__ int smem[512];
    smem[threadIdx.x] = (i < n) ? g_cnt[i] : 0;
    __syncthreads();
    for (int o = 256; o; o >>= 1) {
        if (threadIdx.x < o) smem[threadIdx.x] += smem[threadIdx.x + o];
        __syncthreads();
    }
    if (threadIdx.x == 0) g_part[blockIdx.x] = smem[0];
}

__global__ void k_scan2(int n, int nb) {
    __shared__ int smem[256];
    int t = threadIdx.x;
    int v = (t < nb) ? g_part[t] : 0;
    smem[t] = v;
    __syncthreads();
    for (int o = 1; o < 256; o <<= 1) {
        int x = (t >= o) ? smem[t - o] : 0;
        __syncthreads();
        smem[t] += x;
        __syncthreads();
    }
    int incl = smem[t];
    if (t < nb) g_part[t] = incl - v;
    if (t == nb - 1) g_off[n] = incl;
}

__global__ void k_scan3(int n) {
    int i = blockIdx.x * 512 + threadIdx.x;
    __shared__ int smem[512];
    int t = threadIdx.x;
    int v = (i < n) ? g_cnt[i] : 0;
    smem[t] = v;
    __syncthreads();
    for (int o = 1; o < 512; o <<= 1) {
        int x = (t >= o) ? smem[t - o] : 0;
        __syncthreads();
        smem[t] += x;
        __syncthreads();
    }
    int excl = smem[t] - v;
    if (i < n) {
        int off = g_part[blockIdx.x] + excl;
        g_off[i] = off;
        g_cur[i] = off;
    }
}

// ---------------- decision-filtered scatter ----------------
__global__ void k_scatter(const int* __restrict__ e0, const int* __restrict__ e1,
                          int E, int eBlocks) {
    int set = (blockIdx.x >= eBlocks) ? 1 : 0;
    int i = (blockIdx.x - set * eBlocks) * blockDim.x + threadIdx.x;
    if (i >= E) return;
    int is64 = g_is64;
    const int* e = set ? e1 : e0;
    int s = is64 ? e[2 * i] : e[i];
    int d = is64 ? e[2 * (E + i)] : e[E + i];
    if (g_dec[d] != set) return;
    int p = atomicAdd(&g_cur[d], 1);
    if (p >= 0 && p < 2 * MAXE) g_csr[p] = s;
}

// ---------------- gated aggregation (combined CSR, gate precomputed) ----------------
__global__ __launch_bounds__(256) void k_agg(const float* __restrict__ att,
                                             const float* __restrict__ bias,
                                             float* __restrict__ out, int n) {
    int w = (blockIdx.x * blockDim.x + threadIdx.x) >> 5;
    if (w >= n) return;
    int lane = threadIdx.x & 31;
    int beg = g_off[w], end = g_off[w + 1];

    float4 a4 = *(const float4*)(att + lane * 4);
    const float4* xlp = (const float4*)g_xl;
    float4 r4 = *((const float4*)(g_xr) + (size_t)w * 32 + lane);

    // self loop
    float4 v = xlp[(size_t)w * 32 + lane];
    float p = a4.x * lrelu(v.x + r4.x) + a4.y * lrelu(v.y + r4.y) +
              a4.z * lrelu(v.z + r4.z) + a4.w * lrelu(v.w + r4.w);
    float e = warp_sum(p);
    float wt = __expf(fminf(e, 75.f));
    float s = wt;
    float4 acc = make_float4(wt * v.x, wt * v.y, wt * v.z, wt * v.w);

#pragma unroll 2
    for (int j = beg; j < end; j++) {
        int src = __ldg(&g_csr[j]);
        float4 u = xlp[(size_t)src * 32 + lane];
        float q = a4.x * lrelu(u.x + r4.x) + a4.y * lrelu(u.y + r4.y) +
                  a4.z * lrelu(u.z + r4.z) + a4.w * lrelu(u.w + r4.w);
        float e2 = warp_sum(q);
        float w2 = __expf(fminf(e2, 75.f));
        s += w2;
        acc.x += w2 * u.x; acc.y += w2 * u.y; acc.z += w2 * u.z; acc.w += w2 * u.w;
    }

    float g = g_gate[w];
    float inv = g / (s + 1e-16f);
    float4 b4 = *(const float4*)(bias + lane * 4);
    float4 o4 = make_float4(acc.x * inv + b4.x * g, acc.y * inv + b4.y * g,
                            acc.z * inv + b4.z * g, acc.w * inv + b4.w * g);
    *((float4*)out + (size_t)w * 32 + lane) = o4;
}

// ---------------- launcher ----------------
extern "C" void kernel_launch(void* const* d_in, const int* in_sizes, int n_in,
                              void* d_out, int out_size) {
    const float* x      = (const float*)d_in[0];
    const int*   e_dec  = (const int*)d_in[1];
    const int*   e0     = (const int*)d_in[2];
    const int*   e1     = (const int*)d_in[3];
    const float* gum    = (const float*)d_in[4];
    const float* Wl_g   = (const float*)d_in[5];
    const float* Wr_g   = (const float*)d_in[6];
    const float* bl_g   = (const float*)d_in[7];
    const float* br_g   = (const float*)d_in[8];
    const float* att_g  = (const float*)d_in[9];
    const float* bias_g = (const float*)d_in[10];
    const float* Wl_d   = (const float*)d_in[11];
    const float* Wr_d   = (const float*)d_in[12];
    const float* bl_d   = (const float*)d_in[13];
    const float* br_d   = (const float*)d_in[14];
    const float* att_d  = (const float*)d_in[15];
    const float* bias_d = (const float*)d_in[16];
    float* out = (float*)d_out;

    const int n = in_sizes[0] / 128;
    const int E = in_sizes[1] / 2;
    const int nb = (n + 511) / 512;
    const int eBlocks = (E + 255) / 256;

    cudaFuncSetAttribute(k_mma2, cudaFuncAttributeMaxDynamicSharedMemorySize, SM_GEMM_TOTAL);

    k_detect<<<1, 32>>>(e_dec);                                   // 1
    k_zero<<<(2 * n + 255) / 256, 256>>>(n);                      // 2
    k_prepW<<<128, 256>>>(Wl_g, Wr_g);                            // 3
    k_gemmd<<<(n + 7) / 8, 256>>>(x, Wl_d, Wr_d, bl_d, br_d, n);  // 4
    k_dec_edges<<<eBlocks, 256>>>(e_dec, att_d, E);               // 5
    k_mma2<<<(n + 127) / 128, 512, SM_GEMM_TOTAL>>>(x, bl_g, br_g, n);  // 6 (profiled)
    k_dec_final<<<(n + 255) / 256, 256>>>(gum, att_d, bias_d, n); // 7
    k_hist<<<2 * eBlocks, 256>>>(e0, e1, E, eBlocks);             // 8
    k_scan1<<<nb, 512>>>(n);                                      // 9
    k_scan2<<<1, 256>>>(n, nb);                                   // 10
    k_scan3<<<nb, 512>>>(n);                                      // 11
    k_scatter<<<2 * eBlocks, 256>>>(e0, e1, E, eBlocks);          // 12
    k_agg<<<(n + 7) / 8, 256>>>(att_g, bias_g, out, n);           // 13
}

// round 6
// speedup vs baseline: 1.5262x; 1.5262x over previous
#include <cuda_runtime.h>
#include <cuda_bf16.h>
#include <cstdint>

#define MAXN 100000
#define MAXE 1600000

// ---------------- device scratch ----------------
__device__ __align__(16) float g_xl[(size_t)MAXN * 128];
__device__ __align__(16) float g_xr[(size_t)MAXN * 128];
__device__ float g_xld[MAXN * 2];
__device__ float g_xrd[MAXN * 2];
__device__ float g_sdec[MAXN];
__device__ float g_accdec[MAXN * 2];
__device__ int   g_cnt0[MAXN], g_cnt1[MAXN];
__device__ int   g_off0[MAXN + 1], g_off1[MAXN + 1];
__device__ int   g_cur0[MAXN], g_cur1[MAXN];
__device__ int   g_csr0[MAXE], g_csr1[MAXE];
__device__ int   g_part[512];
__device__ int   g_is64;
// W^T bf16 hi/lo, layout [n][k] (k contiguous): [Wl_hi, Wl_lo, Wr_hi, Wr_lo]
__device__ __align__(16) __nv_bfloat16 g_wtb[4][16384];

// ---------------- helpers ----------------
__device__ __forceinline__ float lrelu(float v) { return v > 0.f ? v : 0.2f * v; }

__device__ __forceinline__ float warp_sum(float v) {
#pragma unroll
    for (int o = 16; o; o >>= 1) v += __shfl_xor_sync(0xffffffffu, v, o);
    return v;
}

__device__ __forceinline__ uint32_t smem_u32(const void* p) {
    uint32_t a;
    asm("{ .reg .u64 t; cvta.to.shared.u64 t, %1; cvt.u32.u64 %0, t; }" : "=r"(a) : "l"(p));
    return a;
}

__device__ __forceinline__ void ldsm_x4(uint32_t* r, uint32_t addr) {
    asm volatile("ldmatrix.sync.aligned.m8n8.x4.shared.b16 {%0,%1,%2,%3}, [%4];"
                 : "=r"(r[0]), "=r"(r[1]), "=r"(r[2]), "=r"(r[3]) : "r"(addr));
}
__device__ __forceinline__ void ldsm_x2(uint32_t* r, uint32_t addr) {
    asm volatile("ldmatrix.sync.aligned.m8n8.x2.shared.b16 {%0,%1}, [%2];"
                 : "=r"(r[0]), "=r"(r[1]) : "r"(addr));
}
__device__ __forceinline__ void mma16816(float* d, const uint32_t* a, const uint32_t* b) {
    asm volatile(
        "mma.sync.aligned.m16n8k16.row.col.f32.bf16.bf16.f32 "
        "{%0,%1,%2,%3}, {%4,%5,%6,%7}, {%8,%9}, {%0,%1,%2,%3};"
        : "+f"(d[0]), "+f"(d[1]), "+f"(d[2]), "+f"(d[3])
        : "r"(a[0]), "r"(a[1]), "r"(a[2]), "r"(a[3]), "r"(b[0]), "r"(b[1]));
}

// ---------------- dtype detection ----------------
__global__ void k_detect(const int* __restrict__ e) {
    int t = threadIdx.x;
    int nz = e[2 * t + 1] | e[2 * (t + 32) + 1] | e[2 * (t + 64) + 1] | e[2 * (t + 96) + 1];
    unsigned m = __ballot_sync(0xffffffffu, nz != 0);
    if (t == 0) g_is64 = (m == 0) ? 1 : 0;
}

// ---------------- zero scratch ----------------
__global__ void k_zero(int n) {
    int i = blockIdx.x * blockDim.x + threadIdx.x;
    if (i < 2 * n) {
        g_accdec[i] = 0.f;
        if (i < n) { g_sdec[i] = 0.f; g_cnt0[i] = 0; g_cnt1[i] = 0; }
    }
}

// ---------------- W^T bf16 hi/lo prep: g_wtb[.][n*128+k] ----------------
__global__ void k_prepW(const float* __restrict__ wl, const float* __restrict__ wr) {
    int i = blockIdx.x * blockDim.x + threadIdx.x;  // 0..32767
    if (i >= 32768) return;
    int m = i >> 14;
    int rem = i & 16383;
    int k = rem >> 7, nn = rem & 127;   // coalesced read over nn
    float w = (m ? wr : wl)[k * 128 + nn];
    __nv_bfloat16 hi = __float2bfloat16(w);
    __nv_bfloat16 lo = __float2bfloat16(w - __bfloat162float(hi));
    g_wtb[2 * m + 0][nn * 128 + k] = hi;
    g_wtb[2 * m + 1][nn * 128 + k] = lo;
}

// ---------------- bf16 split-K mma.sync GEMM: Y[n,128] = X @ W + bias ----------------
// 3-term: Ah*Bh + Ah*Bl + Al*Bh.  smem slabs of K=64, padded rows of 72 bf16.
#define SLAB_ROW 72
#define SM_A_HI 0
#define SM_A_LO 18432
#define SM_B_HI 36864
#define SM_B_LO 55296
#define SM_GEMM_TOTAL 73728

__global__ __launch_bounds__(256, 2) void k_mma(const float* __restrict__ X,
                                                const float* __restrict__ bias,
                                                int which, int n) {
    extern __shared__ __align__(16) unsigned char sm[];
    __nv_bfloat16* Ah = (__nv_bfloat16*)(sm + SM_A_HI);
    __nv_bfloat16* Al = (__nv_bfloat16*)(sm + SM_A_LO);
    __nv_bfloat16* Bh = (__nv_bfloat16*)(sm + SM_B_HI);
    __nv_bfloat16* Bl = (__nv_bfloat16*)(sm + SM_B_LO);

    const int tid = threadIdx.x;
    const int w = tid >> 5;
    const int lane = tid & 31;
    const int wm = w & 3;            // m quarter (32 rows)
    const int wcol = (w >> 2) * 64;  // n half (64 cols)
    const int mBase = blockIdx.x * 128;

    float acc[2][8][4];
#pragma unroll
    for (int a = 0; a < 2; a++)
#pragma unroll
        for (int b = 0; b < 8; b++)
#pragma unroll
            for (int c = 0; c < 4; c++) acc[a][b][c] = 0.f;

    const __nv_bfloat16* WH = g_wtb[2 * which];
    const __nv_bfloat16* WL = g_wtb[2 * which + 1];

#pragma unroll
    for (int slab = 0; slab < 2; slab++) {
        const int k0 = slab * 64;
#pragma unroll
        for (int it = 0; it < 8; it++) {
            int idx = tid + it * 256;
            int row = idx >> 4;
            int q = idx & 15;
            float4 v = make_float4(0.f, 0.f, 0.f, 0.f);
            int gr = mBase + row;
            if (gr < n) v = __ldg((const float4*)(X + (size_t)gr * 128 + k0) + q);
            __nv_bfloat162 h01 = __floats2bfloat162_rn(v.x, v.y);
            __nv_bfloat162 h23 = __floats2bfloat162_rn(v.z, v.w);
            float2 f01 = __bfloat1622float2(h01);
            float2 f23 = __bfloat1622float2(h23);
            __nv_bfloat162 l01 = __floats2bfloat162_rn(v.x - f01.x, v.y - f01.y);
            __nv_bfloat162 l23 = __floats2bfloat162_rn(v.z - f23.x, v.w - f23.y);
            uint2 hw, lw;
            hw.x = *(uint32_t*)&h01; hw.y = *(uint32_t*)&h23;
            lw.x = *(uint32_t*)&l01; lw.y = *(uint32_t*)&l23;
            *(uint2*)&Ah[row * SLAB_ROW + q * 4] = hw;
            *(uint2*)&Al[row * SLAB_ROW + q * 4] = lw;
        }
#pragma unroll
        for (int it = 0; it < 8; it++) {
            int idx = tid + it * 256;
            int ver = idx >> 10;
            int r = (idx >> 3) & 127;
            int j = idx & 7;
            const float4* src = (const float4*)((ver ? WL : WH) + r * 128 + k0);
            float4 val = __ldg(src + j);
            __nv_bfloat16* dst = (ver ? Bl : Bh) + r * SLAB_ROW + j * 8;
            *(float4*)dst = val;
        }
        __syncthreads();

#pragma unroll
        for (int kb = 0; kb < 4; kb++) {
            uint32_t afh[2][4], afl[2][4];
#pragma unroll
            for (int mb = 0; mb < 2; mb++) {
                int row = wm * 32 + mb * 16 + (lane & 7) + ((lane & 8) ? 8 : 0);
                int colb = kb * 32 + ((lane & 16) ? 16 : 0);
                ldsm_x4(afh[mb], smem_u32(&Ah[row * SLAB_ROW]) + colb);
                ldsm_x4(afl[mb], smem_u32(&Al[row * SLAB_ROW]) + colb);
            }
#pragma unroll
            for (int nb = 0; nb < 8; nb++) {
                int nrow = wcol + nb * 8 + (lane & 7);
                int colb = kb * 32 + ((lane & 8) ? 16 : 0);
                uint32_t bh[2], bl[2];
                ldsm_x2(bh, smem_u32(&Bh[nrow * SLAB_ROW]) + colb);
                ldsm_x2(bl, smem_u32(&Bl[nrow * SLAB_ROW]) + colb);
#pragma unroll
                for (int mb = 0; mb < 2; mb++) {
                    mma16816(acc[mb][nb], afh[mb], bh);
                    mma16816(acc[mb][nb], afh[mb], bl);
                    mma16816(acc[mb][nb], afl[mb], bh);
                }
            }
        }
        __syncthreads();
    }

    float* dst = which ? g_xr : g_xl;
    int g = lane >> 2, tg = lane & 3;
#pragma unroll
    for (int mb = 0; mb < 2; mb++) {
#pragma unroll
        for (int nb = 0; nb < 8; nb++) {
            int col = wcol + nb * 8 + 2 * tg;
            float2 bv = __ldg((const float2*)(bias + col));
            int row0 = mBase + wm * 32 + mb * 16 + g;
            if (row0 < n) {
                float2 o = make_float2(acc[mb][nb][0] + bv.x, acc[mb][nb][1] + bv.y);
                *(float2*)(dst + (size_t)row0 * 128 + col) = o;
            }
            int row1 = row0 + 8;
            if (row1 < n) {
                float2 o = make_float2(acc[mb][nb][2] + bv.x, acc[mb][nb][3] + bv.y);
                *(float2*)(dst + (size_t)row1 * 128 + col) = o;
            }
        }
    }
}

// ---------------- decision projections (exact fp32), 4 nodes/warp for MLP ----------------
__global__ void k_gemmd(const float* __restrict__ x,
                        const float* __restrict__ wl, const float* __restrict__ wr,
                        const float* __restrict__ bl, const float* __restrict__ br, int n) {
    int warp = (blockIdx.x * blockDim.x + threadIdx.x) >> 5;
    int base = warp * 4;
    if (base >= n) return;
    int lane = threadIdx.x & 31;
    const float2* WL = (const float2*)wl;
    const float2* WR = (const float2*)wr;
    float2 wa[4], wb[4];
#pragma unroll
    for (int j = 0; j < 4; j++) {
        wa[j] = __ldg(&WL[lane * 4 + j]);
        wb[j] = __ldg(&WR[lane * 4 + j]);
    }
    int cnt = n - base; if (cnt > 4) cnt = 4;
    float4 xv[4];
#pragma unroll
    for (int t = 0; t < 4; t++)
        xv[t] = (t < cnt) ? __ldg((const float4*)(x + (size_t)(base + t) * 128) + lane)
                          : make_float4(0.f, 0.f, 0.f, 0.f);
    float pl0[4], pl1[4], pr0[4], pr1[4];
#pragma unroll
    for (int t = 0; t < 4; t++) {
        float xs[4] = {xv[t].x, xv[t].y, xv[t].z, xv[t].w};
        pl0[t] = pl1[t] = pr0[t] = pr1[t] = 0.f;
#pragma unroll
        for (int j = 0; j < 4; j++) {
            pl0[t] += xs[j] * wa[j].x; pl1[t] += xs[j] * wa[j].y;
            pr0[t] += xs[j] * wb[j].x; pr1[t] += xs[j] * wb[j].y;
        }
    }
#pragma unroll
    for (int o = 16; o; o >>= 1) {
#pragma unroll
        for (int t = 0; t < 4; t++) {
            pl0[t] += __shfl_xor_sync(0xffffffffu, pl0[t], o);
            pl1[t] += __shfl_xor_sync(0xffffffffu, pl1[t], o);
            pr0[t] += __shfl_xor_sync(0xffffffffu, pr0[t], o);
            pr1[t] += __shfl_xor_sync(0xffffffffu, pr1[t], o);
        }
    }
    if (lane == 0) {
        float b0 = __ldg(&bl[0]), b1 = __ldg(&bl[1]);
        float c0 = __ldg(&br[0]), c1 = __ldg(&br[1]);
#pragma unroll
        for (int t = 0; t < 4; t++)
            if (t < cnt) {
                g_xld[2 * (base + t)]     = pl0[t] + b0;
                g_xld[2 * (base + t) + 1] = pl1[t] + b1;
                g_xrd[2 * (base + t)]     = pr0[t] + c0;
                g_xrd[2 * (base + t) + 1] = pr1[t] + c1;
            }
    }
}

// ---------------- fused edge pass: hist(e0) | hist(e1) | decision edges ----------------
__global__ void k_edges(const int* __restrict__ e0, const int* __restrict__ e1,
                        const int* __restrict__ ed, const float* __restrict__ attd,
                        int E, int eBlocks) {
    int role = blockIdx.x / eBlocks;
    int i = (blockIdx.x - role * eBlocks) * blockDim.x + threadIdx.x;
    if (i >= E) return;
    int is64 = g_is64;
    if (role == 0) {
        int d = is64 ? e0[2 * (E + i)] : e0[E + i];
        atomicAdd(&g_cnt0[d], 1);
    } else if (role == 1) {
        int d = is64 ? e1[2 * (E + i)] : e1[E + i];
        atomicAdd(&g_cnt1[d], 1);
    } else {
        int s = is64 ? ed[2 * i] : ed[i];
        int d = is64 ? ed[2 * (E + i)] : ed[E + i];
        float xl0 = g_xld[2 * s], xl1 = g_xld[2 * s + 1];
        float xr0 = g_xrd[2 * d], xr1 = g_xrd[2 * d + 1];
        float a0 = __ldg(&attd[0]), a1 = __ldg(&attd[1]);
        float ee = a0 * lrelu(xl0 + xr0) + a1 * lrelu(xl1 + xr1);
        float w = expf(fminf(ee, 75.f));
        atomicAdd(&g_sdec[d], w);
        atomicAdd(&g_accdec[2 * d], w * xl0);
        atomicAdd(&g_accdec[2 * d + 1], w * xl1);
    }
}

// ---------------- scans ----------------
__global__ void k_scan1(int n, int nb) {
    int set = (blockIdx.x >= nb) ? 1 : 0;
    int b = blockIdx.x - set * nb;
    int i = b * 512 + threadIdx.x;
    const int* cnt = set ? g_cnt1 : g_cnt0;
    __shared__ int smem[512];
    smem[threadIdx.x] = (i < n) ? cnt[i] : 0;
    __syncthreads();
    for (int o = 256; o; o >>= 1) {
        if (threadIdx.x < o) smem[threadIdx.x] += smem[threadIdx.x + o];
        __syncthreads();
    }
    if (threadIdx.x == 0) g_part[set * 256 + b] = smem[0];
}

__global__ void k_scan2(int n, int nb) {
    __shared__ int smem[256];
    int t = threadIdx.x;
    for (int set = 0; set < 2; set++) {
        int v = (t < nb) ? g_part[set * 256 + t] : 0;
        smem[t] = v;
        __syncthreads();
        for (int o = 1; o < 256; o <<= 1) {
            int x = (t >= o) ? smem[t - o] : 0;
            __syncthreads();
            smem[t] += x;
            __syncthreads();
        }
        int incl = smem[t];
        if (t < nb) g_part[set * 256 + t] = incl - v;
        if (t == nb - 1) { if (set) g_off1[n] = incl; else g_off0[n] = incl; }
        __syncthreads();
    }
}

__global__ void k_scan3(int n, int nb) {
    int set = (blockIdx.x >= nb) ? 1 : 0;
    int b = blockIdx.x - set * nb;
    int i = b * 512 + threadIdx.x;
    const int* cnt = set ? g_cnt1 : g_cnt0;
    __shared__ int smem[512];
    int t = threadIdx.x;
    int v = (i < n) ? cnt[i] : 0;
    smem[t] = v;
    __syncthreads();
    for (int o = 1; o < 512; o <<= 1) {
        int x = (t >= o) ? smem[t - o] : 0;
        __syncthreads();
        smem[t] += x;
        __syncthreads();
    }
    int excl = smem[t] - v;
    if (i < n) {
        int off = g_part[set * 256 + b] + excl;
        if (set) { g_off1[i] = off; g_cur1[i] = off; }
        else     { g_off0[i] = off; g_cur0[i] = off; }
    }
}

// ---------------- fused scatter ----------------
__global__ void k_scatter2(const int* __restrict__ e0, const int* __restrict__ e1,
                           int E, int eBlocks) {
    int set = (blockIdx.x >= eBlocks) ? 1 : 0;
    int i = (blockIdx.x - set * eBlocks) * blockDim.x + threadIdx.x;
    if (i >= E) return;
    int is64 = g_is64;
    const int* e = set ? e1 : e0;
    int s = is64 ? e[2 * i] : e[i];
    int d = is64 ? e[2 * (E + i)] : e[E + i];
    int p = atomicAdd(set ? &g_cur1[d] : &g_cur0[d], 1);
    if (p >= 0 && p < MAXE) { if (set) g_csr1[p] = s; else g_csr0[p] = s; }
}

// ---------------- gated aggregation (decision folded in, 4-edge pipeline) ----------------
__global__ __launch_bounds__(256) void k_agg(const float* __restrict__ att,
                                             const float* __restrict__ bias,
                                             const float* __restrict__ gum,
                                             const float* __restrict__ attd,
                                             const float* __restrict__ biasd,
                                             float* __restrict__ out, int n) {
    int w = (blockIdx.x * blockDim.x + threadIdx.x) >> 5;
    if (w >= n) return;
    int lane = threadIdx.x & 31;

    // --- decision (uniform scalar math, all lanes) ---
    int k;
    float g;
    {
        float xl0 = g_xld[2 * w], xl1 = g_xld[2 * w + 1];
        float xr0 = g_xrd[2 * w], xr1 = g_xrd[2 * w + 1];
        float a0 = __ldg(&attd[0]), a1 = __ldg(&attd[1]);
        float ee = a0 * lrelu(xl0 + xr0) + a1 * lrelu(xl1 + xr1);
        float wsl = expf(fminf(ee, 75.f));
        float s = g_sdec[w] + wsl;
        float A0 = g_accdec[2 * w] + wsl * xl0;
        float A1 = g_accdec[2 * w + 1] + wsl * xl1;
        float inv = 1.f / (s + 1e-16f);
        float l0 = A0 * inv + __ldg(&biasd[0]);
        float l1 = A1 * inv + __ldg(&biasd[1]);
        float z0 = (l0 + gum[2 * w]) * 2.0f;
        float z1 = (l1 + gum[2 * w + 1]) * 2.0f;
        k = (z0 >= z1) ? 0 : 1;
        float du = (k == 0) ? (z1 - z0) : (z0 - z1);
        float p = 1.f / (1.f + expf(du));
        volatile float t = 1.0f + p;
        g = t - p;
    }

    const int* csr = k ? g_csr1 : g_csr0;
    const int* off = k ? g_off1 : g_off0;
    int beg = off[w], end = off[w + 1];

    float4 a4 = *(const float4*)(att + lane * 4);
    const float4* xlp = (const float4*)g_xl;
    float4 r4 = *((const float4*)(g_xr) + (size_t)w * 32 + lane);

    // self loop
    float4 v = xlp[(size_t)w * 32 + lane];
    float p = a4.x * lrelu(v.x + r4.x) + a4.y * lrelu(v.y + r4.y) +
              a4.z * lrelu(v.z + r4.z) + a4.w * lrelu(v.w + r4.w);
    float e = warp_sum(p);
    float wt = __expf(fminf(e, 75.f));
    float s = wt;
    float4 acc = make_float4(wt * v.x, wt * v.y, wt * v.z, wt * v.w);

    int j = beg;
#pragma unroll 1
    for (; j + 4 <= end; j += 4) {
        int s0 = __ldg(&csr[j]);
        int s1 = __ldg(&csr[j + 1]);
        int s2 = __ldg(&csr[j + 2]);
        int s3 = __ldg(&csr[j + 3]);
        float4 u0 = xlp[(size_t)s0 * 32 + lane];
        float4 u1 = xlp[(size_t)s1 * 32 + lane];
        float4 u2 = xlp[(size_t)s2 * 32 + lane];
        float4 u3 = xlp[(size_t)s3 * 32 + lane];
        float q0 = a4.x * lrelu(u0.x + r4.x) + a4.y * lrelu(u0.y + r4.y) +
                   a4.z * lrelu(u0.z + r4.z) + a4.w * lrelu(u0.w + r4.w);
        float q1 = a4.x * lrelu(u1.x + r4.x) + a4.y * lrelu(u1.y + r4.y) +
                   a4.z * lrelu(u1.z + r4.z) + a4.w * lrelu(u1.w + r4.w);
        float q2 = a4.x * lrelu(u2.x + r4.x) + a4.y * lrelu(u2.y + r4.y) +
                   a4.z * lrelu(u2.z + r4.z) + a4.w * lrelu(u2.w + r4.w);
        float q3 = a4.x * lrelu(u3.x + r4.x) + a4.y * lrelu(u3.y + r4.y) +
                   a4.z * lrelu(u3.z + r4.z) + a4.w * lrelu(u3.w + r4.w);
#pragma unroll
        for (int o = 16; o; o >>= 1) {
            q0 += __shfl_xor_sync(0xffffffffu, q0, o);
            q1 += __shfl_xor_sync(0xffffffffu, q1, o);
            q2 += __shfl_xor_sync(0xffffffffu, q2, o);
            q3 += __shfl_xor_sync(0xffffffffu, q3, o);
        }
        float w0 = __expf(fminf(q0, 75.f));
        float w1 = __expf(fminf(q1, 75.f));
        float w2 = __expf(fminf(q2, 75.f));
        float w3 = __expf(fminf(q3, 75.f));
        s += (w0 + w1) + (w2 + w3);
        acc.x += w0 * u0.x + w1 * u1.x + w2 * u2.x + w3 * u3.x;
        acc.y += w0 * u0.y + w1 * u1.y + w2 * u2.y + w3 * u3.y;
        acc.z += w0 * u0.z + w1 * u1.z + w2 * u2.z + w3 * u3.z;
        acc.w += w0 * u0.w + w1 * u1.w + w2 * u2.w + w3 * u3.w;
    }
#pragma unroll 1
    for (; j < end; j++) {
        int src = __ldg(&csr[j]);
        float4 u = xlp[(size_t)src * 32 + lane];
        float q = a4.x * lrelu(u.x + r4.x) + a4.y * lrelu(u.y + r4.y) +
                  a4.z * lrelu(u.z + r4.z) + a4.w * lrelu(u.w + r4.w);
        float e2 = warp_sum(q);
        float w2 = __expf(fminf(e2, 75.f));
        s += w2;
        acc.x += w2 * u.x; acc.y += w2 * u.y; acc.z += w2 * u.z; acc.w += w2 * u.w;
    }

    float inv = g / (s + 1e-16f);
    float4 b4 = *(const float4*)(bias + lane * 4);
    float4 o4 = make_float4(acc.x * inv + b4.x * g, acc.y * inv + b4.y * g,
                            acc.z * inv + b4.z * g, acc.w * inv + b4.w * g);
    *((float4*)out + (size_t)w * 32 + lane) = o4;
}

// ---------------- launcher ----------------
extern "C" void kernel_launch(void* const* d_in, const int* in_sizes, int n_in,
                              void* d_out, int out_size) {
    const float* x      = (const float*)d_in[0];
    const int*   e_dec  = (const int*)d_in[1];
    const int*   e0     = (const int*)d_in[2];
    const int*   e1     = (const int*)d_in[3];
    const float* gum    = (const float*)d_in[4];
    const float* Wl_g   = (const float*)d_in[5];
    const float* Wr_g   = (const float*)d_in[6];
    const float* bl_g   = (const float*)d_in[7];
    const float* br_g   = (const float*)d_in[8];
    const float* att_g  = (const float*)d_in[9];
    const float* bias_g = (const float*)d_in[10];
    const float* Wl_d   = (const float*)d_in[11];
    const float* Wr_d   = (const float*)d_in[12];
    const float* bl_d   = (const float*)d_in[13];
    const float* br_d   = (const float*)d_in[14];
    const float* att_d  = (const float*)d_in[15];
    const float* bias_d = (const float*)d_in[16];
    float* out = (float*)d_out;

    const int n = in_sizes[0] / 128;
    const int E = in_sizes[1] / 2;
    const int nb = (n + 511) / 512;
    const int eBlocks = (E + 255) / 256;

    cudaFuncSetAttribute(k_mma, cudaFuncAttributeMaxDynamicSharedMemorySize, SM_GEMM_TOTAL);

    k_detect<<<1, 32>>>(e_dec);
    k_zero<<<(2 * n + 255) / 256, 256>>>(n);
    k_prepW<<<128, 256>>>(Wl_g, Wr_g);

    const int gBlocks = (n + 127) / 128;
    k_mma<<<gBlocks, 256, SM_GEMM_TOTAL>>>(x, bl_g, 0, n);
    k_mma<<<gBlocks, 256, SM_GEMM_TOTAL>>>(x, br_g, 1, n);
    k_gemmd<<<(n + 31) / 32, 256>>>(x, Wl_d, Wr_d, bl_d, br_d, n);

    k_edges<<<3 * eBlocks, 256>>>(e0, e1, e_dec, att_d, E, eBlocks);

    k_scan1<<<2 * nb, 512>>>(n, nb);
    k_scan2<<<1, 256>>>(n, nb);
    k_scan3<<<2 * nb, 512>>>(n, nb);

    k_scatter2<<<2 * eBlocks, 256>>>(e0, e1, E, eBlocks);

    k_agg<<<(n + 7) / 8, 256>>>(att_g, bias_g, gum, att_d, bias_d, out, n);
}

// round 7
// speedup vs baseline: 1.5887x; 1.0410x over previous
#include <cuda_runtime.h>
#include <cuda_bf16.h>
#include <cstdint>

#define MAXN 100000
#define MAXE 1600000

// ---------------- device scratch ----------------
__device__ __align__(16) float g_xl[(size_t)MAXN * 128];
__device__ __align__(16) float g_xr[(size_t)MAXN * 128];
__device__ float g_xld[MAXN * 2];
__device__ float g_xrd[MAXN * 2];
__device__ float g_sdec[MAXN];
__device__ float g_accdec[MAXN * 2];
__device__ int   g_cnt0[MAXN], g_cnt1[MAXN];
__device__ int   g_off0[MAXN + 1], g_off1[MAXN + 1];
__device__ int   g_cur0[MAXN], g_cur1[MAXN];
__device__ int   g_csr0[MAXE], g_csr1[MAXE];
__device__ int   g_part[512];
__device__ int   g_is64;
// W^T bf16 hi/lo, layout [n][k] (k contiguous): [Wl_hi, Wl_lo, Wr_hi, Wr_lo]
__device__ __align__(16) __nv_bfloat16 g_wtb[4][16384];

// ---------------- helpers ----------------
__device__ __forceinline__ float lrelu(float v) { return v > 0.f ? v : 0.2f * v; }

__device__ __forceinline__ float warp_sum(float v) {
#pragma unroll
    for (int o = 16; o; o >>= 1) v += __shfl_xor_sync(0xffffffffu, v, o);
    return v;
}

__device__ __forceinline__ uint32_t smem_u32(const void* p) {
    uint32_t a;
    asm("{ .reg .u64 t; cvta.to.shared.u64 t, %1; cvt.u32.u64 %0, t; }" : "=r"(a) : "l"(p));
    return a;
}

__device__ __forceinline__ void ldsm_x4(uint32_t* r, uint32_t addr) {
    asm volatile("ldmatrix.sync.aligned.m8n8.x4.shared.b16 {%0,%1,%2,%3}, [%4];"
                 : "=r"(r[0]), "=r"(r[1]), "=r"(r[2]), "=r"(r[3]) : "r"(addr));
}
__device__ __forceinline__ void mma16816(float* d, const uint32_t* a, const uint32_t* b) {
    asm volatile(
        "mma.sync.aligned.m16n8k16.row.col.f32.bf16.bf16.f32 "
        "{%0,%1,%2,%3}, {%4,%5,%6,%7}, {%8,%9}, {%0,%1,%2,%3};"
        : "+f"(d[0]), "+f"(d[1]), "+f"(d[2]), "+f"(d[3])
        : "r"(a[0]), "r"(a[1]), "r"(a[2]), "r"(a[3]), "r"(b[0]), "r"(b[1]));
}

// ---------------- fused setup: zero | prepW | detect ----------------
__global__ void k_setup(const int* __restrict__ ed,
                        const float* __restrict__ wl, const float* __restrict__ wr,
                        int n, int zBlocks) {
    int b = blockIdx.x;
    if (b < zBlocks) {                     // zero role
        int i = b * 256 + threadIdx.x;
        if (i < 2 * n) {
            g_accdec[i] = 0.f;
            if (i < n) { g_sdec[i] = 0.f; g_cnt0[i] = 0; g_cnt1[i] = 0; }
        }
        return;
    }
    if (b < zBlocks + 128) {               // prepW role
        int i = (b - zBlocks) * 256 + threadIdx.x;  // 0..32767
        int m = i >> 14;
        int rem = i & 16383;
        int k = rem >> 7, nn = rem & 127;
        float w = (m ? wr : wl)[k * 128 + nn];
        __nv_bfloat16 hi = __float2bfloat16(w);
        __nv_bfloat16 lo = __float2bfloat16(w - __bfloat162float(hi));
        g_wtb[2 * m + 0][nn * 128 + k] = hi;
        g_wtb[2 * m + 1][nn * 128 + k] = lo;
        return;
    }
    // detect role (one block; first warp)
    if (threadIdx.x < 32) {
        int t = threadIdx.x;
        int nz = ed[2 * t + 1] | ed[2 * (t + 32) + 1] | ed[2 * (t + 64) + 1] |
                 ed[2 * (t + 96) + 1];
        unsigned m = __ballot_sync(0xffffffffu, nz != 0);
        if (t == 0) g_is64 = (m == 0) ? 1 : 0;
    }
}

// ---------------- bf16 split-K mma.sync GEMM (both outputs, one grid) ----------------
// 3-term: Ah*Bh + Ah*Bl + Al*Bh.  smem slabs of K=64, padded rows of 72 bf16.
#define SLAB_ROW 72
#define SM_A_HI 0
#define SM_A_LO 18432
#define SM_B_HI 36864
#define SM_B_LO 55296
#define SM_GEMM_TOTAL 73728

__global__ __launch_bounds__(256, 2) void k_mma(const float* __restrict__ X,
                                                const float* __restrict__ bl,
                                                const float* __restrict__ br,
                                                int gBlocks, int n) {
    extern __shared__ __align__(16) unsigned char sm[];
    __nv_bfloat16* Ah = (__nv_bfloat16*)(sm + SM_A_HI);
    __nv_bfloat16* Al = (__nv_bfloat16*)(sm + SM_A_LO);
    __nv_bfloat16* Bh = (__nv_bfloat16*)(sm + SM_B_HI);
    __nv_bfloat16* Bl = (__nv_bfloat16*)(sm + SM_B_LO);

    const int which = (blockIdx.x >= gBlocks) ? 1 : 0;
    const int mBase = (blockIdx.x - which * gBlocks) * 128;
    const int tid = threadIdx.x;
    const int w = tid >> 5;
    const int lane = tid & 31;
    const int wm = w & 3;            // m quarter (32 rows)
    const int wcol = (w >> 2) * 64;  // n half (64 cols)

    float acc[2][8][4];
#pragma unroll
    for (int a = 0; a < 2; a++)
#pragma unroll
        for (int b = 0; b < 8; b++)
#pragma unroll
            for (int c = 0; c < 4; c++) acc[a][b][c] = 0.f;

    const __nv_bfloat16* WH = g_wtb[2 * which];
    const __nv_bfloat16* WL = g_wtb[2 * which + 1];

#pragma unroll
    for (int slab = 0; slab < 2; slab++) {
        const int k0 = slab * 64;
#pragma unroll
        for (int it = 0; it < 8; it++) {
            int idx = tid + it * 256;
            int row = idx >> 4;
            int q = idx & 15;
            float4 v = make_float4(0.f, 0.f, 0.f, 0.f);
            int gr = mBase + row;
            if (gr < n) v = __ldg((const float4*)(X + (size_t)gr * 128 + k0) + q);
            __nv_bfloat162 h01 = __floats2bfloat162_rn(v.x, v.y);
            __nv_bfloat162 h23 = __floats2bfloat162_rn(v.z, v.w);
            float2 f01 = __bfloat1622float2(h01);
            float2 f23 = __bfloat1622float2(h23);
            __nv_bfloat162 l01 = __floats2bfloat162_rn(v.x - f01.x, v.y - f01.y);
            __nv_bfloat162 l23 = __floats2bfloat162_rn(v.z - f23.x, v.w - f23.y);
            uint2 hw, lw;
            hw.x = *(uint32_t*)&h01; hw.y = *(uint32_t*)&h23;
            lw.x = *(uint32_t*)&l01; lw.y = *(uint32_t*)&l23;
            *(uint2*)&Ah[row * SLAB_ROW + q * 4] = hw;
            *(uint2*)&Al[row * SLAB_ROW + q * 4] = lw;
        }
#pragma unroll
        for (int it = 0; it < 8; it++) {
            int idx = tid + it * 256;
            int ver = idx >> 10;
            int r = (idx >> 3) & 127;
            int j = idx & 7;
            const float4* src = (const float4*)((ver ? WL : WH) + r * 128 + k0);
            float4 val = __ldg(src + j);
            __nv_bfloat16* dst = (ver ? Bl : Bh) + r * SLAB_ROW + j * 8;
            *(float4*)dst = val;
        }
        __syncthreads();

#pragma unroll
        for (int kb = 0; kb < 4; kb++) {
            uint32_t afh[2][4], afl[2][4];
#pragma unroll
            for (int mb = 0; mb < 2; mb++) {
                int row = wm * 32 + mb * 16 + (lane & 7) + ((lane & 8) ? 8 : 0);
                int colb = kb * 32 + ((lane & 16) ? 16 : 0);
                ldsm_x4(afh[mb], smem_u32(&Ah[row * SLAB_ROW]) + colb);
                ldsm_x4(afl[mb], smem_u32(&Al[row * SLAB_ROW]) + colb);
            }
            // B fragments: x4 over nb pairs -> regs [0,1]=nb, [2,3]=nb+1
#pragma unroll
            for (int np = 0; np < 4; np++) {
                int nrow = wcol + np * 16 + ((lane & 16) ? 8 : 0) + (lane & 7);
                int colb = kb * 32 + ((lane & 8) ? 16 : 0);
                uint32_t bh[4], bl[4];
                ldsm_x4(bh, smem_u32(&Bh[nrow * SLAB_ROW]) + colb);
                ldsm_x4(bl, smem_u32(&Bl[nrow * SLAB_ROW]) + colb);
#pragma unroll
                for (int half = 0; half < 2; half++) {
                    int nb = np * 2 + half;
#pragma unroll
                    for (int mb = 0; mb < 2; mb++) {
                        mma16816(acc[mb][nb], afh[mb], bh + 2 * half);
                        mma16816(acc[mb][nb], afh[mb], bl + 2 * half);
                        mma16816(acc[mb][nb], afl[mb], bh + 2 * half);
                    }
                }
            }
        }
        __syncthreads();
    }

    float* dst = which ? g_xr : g_xl;
    const float* bias = which ? br : bl;
    int g = lane >> 2, tg = lane & 3;
#pragma unroll
    for (int mb = 0; mb < 2; mb++) {
#pragma unroll
        for (int nb = 0; nb < 8; nb++) {
            int col = wcol + nb * 8 + 2 * tg;
            float2 bv = __ldg((const float2*)(bias + col));
            int row0 = mBase + wm * 32 + mb * 16 + g;
            if (row0 < n) {
                float2 o = make_float2(acc[mb][nb][0] + bv.x, acc[mb][nb][1] + bv.y);
                *(float2*)(dst + (size_t)row0 * 128 + col) = o;
            }
            int row1 = row0 + 8;
            if (row1 < n) {
                float2 o = make_float2(acc[mb][nb][2] + bv.x, acc[mb][nb][3] + bv.y);
                *(float2*)(dst + (size_t)row1 * 128 + col) = o;
            }
        }
    }
}

// ---------------- decision projections (exact fp32), 4 nodes/warp for MLP ----------------
__global__ void k_gemmd(const float* __restrict__ x,
                        const float* __restrict__ wl, const float* __restrict__ wr,
                        const float* __restrict__ bl, const float* __restrict__ br, int n) {
    int warp = (blockIdx.x * blockDim.x + threadIdx.x) >> 5;
    int base = warp * 4;
    if (base >= n) return;
    int lane = threadIdx.x & 31;
    const float2* WL = (const float2*)wl;
    const float2* WR = (const float2*)wr;
    float2 wa[4], wb[4];
#pragma unroll
    for (int j = 0; j < 4; j++) {
        wa[j] = __ldg(&WL[lane * 4 + j]);
        wb[j] = __ldg(&WR[lane * 4 + j]);
    }
    int cnt = n - base; if (cnt > 4) cnt = 4;
    float4 xv[4];
#pragma unroll
    for (int t = 0; t < 4; t++)
        xv[t] = (t < cnt) ? __ldg((const float4*)(x + (size_t)(base + t) * 128) + lane)
                          : make_float4(0.f, 0.f, 0.f, 0.f);
    float pl0[4], pl1[4], pr0[4], pr1[4];
#pragma unroll
    for (int t = 0; t < 4; t++) {
        float xs[4] = {xv[t].x, xv[t].y, xv[t].z, xv[t].w};
        pl0[t] = pl1[t] = pr0[t] = pr1[t] = 0.f;
#pragma unroll
        for (int j = 0; j < 4; j++) {
            pl0[t] += xs[j] * wa[j].x; pl1[t] += xs[j] * wa[j].y;
            pr0[t] += xs[j] * wb[j].x; pr1[t] += xs[j] * wb[j].y;
        }
    }
#pragma unroll
    for (int o = 16; o; o >>= 1) {
#pragma unroll
        for (int t = 0; t < 4; t++) {
            pl0[t] += __shfl_xor_sync(0xffffffffu, pl0[t], o);
            pl1[t] += __shfl_xor_sync(0xffffffffu, pl1[t], o);
            pr0[t] += __shfl_xor_sync(0xffffffffu, pr0[t], o);
            pr1[t] += __shfl_xor_sync(0xffffffffu, pr1[t], o);
        }
    }
    if (lane == 0) {
        float b0 = __ldg(&bl[0]), b1 = __ldg(&bl[1]);
        float c0 = __ldg(&br[0]), c1 = __ldg(&br[1]);
#pragma unroll
        for (int t = 0; t < 4; t++)
            if (t < cnt) {
                g_xld[2 * (base + t)]     = pl0[t] + b0;
                g_xld[2 * (base + t) + 1] = pl1[t] + b1;
                g_xrd[2 * (base + t)]     = pr0[t] + c0;
                g_xrd[2 * (base + t) + 1] = pr1[t] + c1;
            }
    }
}

// ---------------- fused edge pass: hist(e0) | hist(e1) | decision edges ----------------
__global__ void k_edges(const int* __restrict__ e0, const int* __restrict__ e1,
                        const int* __restrict__ ed, const float* __restrict__ attd,
                        int E, int eBlocks) {
    int role = blockIdx.x / eBlocks;
    int i = (blockIdx.x - role * eBlocks) * blockDim.x + threadIdx.x;
    if (i >= E) return;
    int is64 = g_is64;
    if (role == 0) {
        int d = is64 ? e0[2 * (E + i)] : e0[E + i];
        atomicAdd(&g_cnt0[d], 1);
    } else if (role == 1) {
        int d = is64 ? e1[2 * (E + i)] : e1[E + i];
        atomicAdd(&g_cnt1[d], 1);
    } else {
        int s = is64 ? ed[2 * i] : ed[i];
        int d = is64 ? ed[2 * (E + i)] : ed[E + i];
        float xl0 = g_xld[2 * s], xl1 = g_xld[2 * s + 1];
        float xr0 = g_xrd[2 * d], xr1 = g_xrd[2 * d + 1];
        float a0 = __ldg(&attd[0]), a1 = __ldg(&attd[1]);
        float ee = a0 * lrelu(xl0 + xr0) + a1 * lrelu(xl1 + xr1);
        float w = expf(fminf(ee, 75.f));
        atomicAdd(&g_sdec[d], w);
        atomicAdd(&g_accdec[2 * d], w * xl0);
        atomicAdd(&g_accdec[2 * d + 1], w * xl1);
    }
}

// ---------------- scans ----------------
__global__ void k_scan1(int n, int nb) {
    int set = (blockIdx.x >= nb) ? 1 : 0;
    int b = blockIdx.x - set * nb;
    int i = b * 512 + threadIdx.x;
    const int* cnt = set ? g_cnt1 : g_cnt0;
    __shared__ int smem[512];
    smem[threadIdx.x] = (i < n) ? cnt[i] : 0;
    __syncthreads();
    for (int o = 256; o; o >>= 1) {
        if (threadIdx.x < o) smem[threadIdx.x] += smem[threadIdx.x + o];
        __syncthreads();
    }
    if (threadIdx.x == 0) g_part[set * 256 + b] = smem[0];
}

__global__ void k_scan2(int n, int nb) {
    __shared__ int smem[256];
    int t = threadIdx.x;
    for (int set = 0; set < 2; set++) {
        int v = (t < nb) ? g_part[set * 256 + t] : 0;
        smem[t] = v;
        __syncthreads();
        for (int o = 1; o < 256; o <<= 1) {
            int x = (t >= o) ? smem[t - o] : 0;
            __syncthreads();
            smem[t] += x;
            __syncthreads();
        }
        int incl = smem[t];
        if (t < nb) g_part[set * 256 + t] = incl - v;
        if (t == nb - 1) { if (set) g_off1[n] = incl; else g_off0[n] = incl; }
        __syncthreads();
    }
}

__global__ void k_scan3(int n, int nb) {
    int set = (blockIdx.x >= nb) ? 1 : 0;
    int b = blockIdx.x - set * nb;
    int i = b * 512 + threadIdx.x;
    const int* cnt = set ? g_cnt1 : g_cnt0;
    __shared__ int smem[512];
    int t = threadIdx.x;
    int v = (i < n) ? cnt[i] : 0;
    smem[t] = v;
    __syncthreads();
    for (int o = 1; o < 512; o <<= 1) {
        int x = (t >= o) ? smem[t - o] : 0;
        __syncthreads();
        smem[t] += x;
        __syncthreads();
    }
    int excl = smem[t] - v;
    if (i < n) {
        int off = g_part[set * 256 + b] + excl;
        if (set) { g_off1[i] = off; g_cur1[i] = off; }
        else     { g_off0[i] = off; g_cur0[i] = off; }
    }
}

// ---------------- fused scatter ----------------
__global__ void k_scatter2(const int* __restrict__ e0, const int* __restrict__ e1,
                           int E, int eBlocks) {
    int set = (blockIdx.x >= eBlocks) ? 1 : 0;
    int i = (blockIdx.x - set * eBlocks) * blockDim.x + threadIdx.x;
    if (i >= E) return;
    int is64 = g_is64;
    const int* e = set ? e1 : e0;
    int s = is64 ? e[2 * i] : e[i];
    int d = is64 ? e[2 * (E + i)] : e[E + i];
    int p = atomicAdd(set ? &g_cur1[d] : &g_cur0[d], 1);
    if (p >= 0 && p < MAXE) { if (set) g_csr1[p] = s; else g_csr0[p] = s; }
}

// ---------------- gated aggregation (decision folded in, 4-edge pipeline) ----------------
__global__ __launch_bounds__(256) void k_agg(const float* __restrict__ att,
                                             const float* __restrict__ bias,
                                             const float* __restrict__ gum,
                                             const float* __restrict__ attd,
                                             const float* __restrict__ biasd,
                                             float* __restrict__ out, int n) {
    int w = (blockIdx.x * blockDim.x + threadIdx.x) >> 5;
    if (w >= n) return;
    int lane = threadIdx.x & 31;

    int k;
    float g;
    {
        float xl0 = g_xld[2 * w], xl1 = g_xld[2 * w + 1];
        float xr0 = g_xrd[2 * w], xr1 = g_xrd[2 * w + 1];
        float a0 = __ldg(&attd[0]), a1 = __ldg(&attd[1]);
        float ee = a0 * lrelu(xl0 + xr0) + a1 * lrelu(xl1 + xr1);
        float wsl = expf(fminf(ee, 75.f));
        float s = g_sdec[w] + wsl;
        float A0 = g_accdec[2 * w] + wsl * xl0;
        float A1 = g_accdec[2 * w + 1] + wsl * xl1;
        float inv = 1.f / (s + 1e-16f);
        float l0 = A0 * inv + __ldg(&biasd[0]);
        float l1 = A1 * inv + __ldg(&biasd[1]);
        float z0 = (l0 + gum[2 * w]) * 2.0f;
        float z1 = (l1 + gum[2 * w + 1]) * 2.0f;
        k = (z0 >= z1) ? 0 : 1;
        float du = (k == 0) ? (z1 - z0) : (z0 - z1);
        float p = 1.f / (1.f + expf(du));
        volatile float t = 1.0f + p;
        g = t - p;
    }

    const int* csr = k ? g_csr1 : g_csr0;
    const int* off = k ? g_off1 : g_off0;
    int beg = off[w], end = off[w + 1];

    float4 a4 = *(const float4*)(att + lane * 4);
    const float4* xlp = (const float4*)g_xl;
    float4 r4 = *((const float4*)(g_xr) + (size_t)w * 32 + lane);

    float4 v = xlp[(size_t)w * 32 + lane];
    float p = a4.x * lrelu(v.x + r4.x) + a4.y * lrelu(v.y + r4.y) +
              a4.z * lrelu(v.z + r4.z) + a4.w * lrelu(v.w + r4.w);
    float e = warp_sum(p);
    float wt = __expf(fminf(e, 75.f));
    float s = wt;
    float4 acc = make_float4(wt * v.x, wt * v.y, wt * v.z, wt * v.w);

    int j = beg;
#pragma unroll 1
    for (; j + 4 <= end; j += 4) {
        int s0 = __ldg(&csr[j]);
        int s1 = __ldg(&csr[j + 1]);
        int s2 = __ldg(&csr[j + 2]);
        int s3 = __ldg(&csr[j + 3]);
        float4 u0 = xlp[(size_t)s0 * 32 + lane];
        float4 u1 = xlp[(size_t)s1 * 32 + lane];
        float4 u2 = xlp[(size_t)s2 * 32 + lane];
        float4 u3 = xlp[(size_t)s3 * 32 + lane];
        float q0 = a4.x * lrelu(u0.x + r4.x) + a4.y * lrelu(u0.y + r4.y) +
                   a4.z * lrelu(u0.z + r4.z) + a4.w * lrelu(u0.w + r4.w);
        float q1 = a4.x * lrelu(u1.x + r4.x) + a4.y * lrelu(u1.y + r4.y) +
                   a4.z * lrelu(u1.z + r4.z) + a4.w * lrelu(u1.w + r4.w);
        float q2 = a4.x * lrelu(u2.x + r4.x) + a4.y * lrelu(u2.y + r4.y) +
                   a4.z * lrelu(u2.z + r4.z) + a4.w * lrelu(u2.w + r4.w);
        float q3 = a4.x * lrelu(u3.x + r4.x) + a4.y * lrelu(u3.y + r4.y) +
                   a4.z * lrelu(u3.z + r4.z) + a4.w * lrelu(u3.w + r4.w);
#pragma unroll
        for (int o = 16; o; o >>= 1) {
            q0 += __shfl_xor_sync(0xffffffffu, q0, o);
            q1 += __shfl_xor_sync(0xffffffffu, q1, o);
            q2 += __shfl_xor_sync(0xffffffffu, q2, o);
            q3 += __shfl_xor_sync(0xffffffffu, q3, o);
        }
        float w0 = __expf(fminf(q0, 75.f));
        float w1 = __expf(fminf(q1, 75.f));
        float w2 = __expf(fminf(q2, 75.f));
        float w3 = __expf(fminf(q3, 75.f));
        s += (w0 + w1) + (w2 + w3);
        acc.x += w0 * u0.x + w1 * u1.x + w2 * u2.x + w3 * u3.x;
        acc.y += w0 * u0.y + w1 * u1.y + w2 * u2.y + w3 * u3.y;
        acc.z += w0 * u0.z + w1 * u1.z + w2 * u2.z + w3 * u3.z;
        acc.w += w0 * u0.w + w1 * u1.w + w2 * u2.w + w3 * u3.w;
    }
#pragma unroll 1
    for (; j < end; j++) {
        int src = __ldg(&csr[j]);
        float4 u = xlp[(size_t)src * 32 + lane];
        float q = a4.x * lrelu(u.x + r4.x) + a4.y * lrelu(u.y + r4.y) +
                  a4.z * lrelu(u.z + r4.z) + a4.w * lrelu(u.w + r4.w);
        float e2 = warp_sum(q);
        float w2 = __expf(fminf(e2, 75.f));
        s += w2;
        acc.x += w2 * u.x; acc.y += w2 * u.y; acc.z += w2 * u.z; acc.w += w2 * u.w;
    }

    float inv = g / (s + 1e-16f);
    float4 b4 = *(const float4*)(bias + lane * 4);
    float4 o4 = make_float4(acc.x * inv + b4.x * g, acc.y * inv + b4.y * g,
                            acc.z * inv + b4.z * g, acc.w * inv + b4.w * g);
    *((float4*)out + (size_t)w * 32 + lane) = o4;
}

// ---------------- launcher ----------------
extern "C" void kernel_launch(void* const* d_in, const int* in_sizes, int n_in,
                              void* d_out, int out_size) {
    const float* x      = (const float*)d_in[0];
    const int*   e_dec  = (const int*)d_in[1];
    const int*   e0     = (const int*)d_in[2];
    const int*   e1     = (const int*)d_in[3];
    const float* gum    = (const float*)d_in[4];
    const float* Wl_g   = (const float*)d_in[5];
    const float* Wr_g   = (const float*)d_in[6];
    const float* bl_g   = (const float*)d_in[7];
    const float* br_g   = (const float*)d_in[8];
    const float* att_g  = (const float*)d_in[9];
    const float* bias_g = (const float*)d_in[10];
    const float* Wl_d   = (const float*)d_in[11];
    const float* Wr_d   = (const float*)d_in[12];
    const float* bl_d   = (const float*)d_in[13];
    const float* br_d   = (const float*)d_in[14];
    const float* att_d  = (const float*)d_in[15];
    const float* bias_d = (const float*)d_in[16];
    float* out = (float*)d_out;

    const int n = in_sizes[0] / 128;
    const int E = in_sizes[1] / 2;
    const int nb = (n + 511) / 512;
    const int eBlocks = (E + 255) / 256;
    const int zBlocks = (2 * n + 255) / 256;

    cudaFuncSetAttribute(k_mma, cudaFuncAttributeMaxDynamicSharedMemorySize, SM_GEMM_TOTAL);

    k_setup<<<zBlocks + 128 + 1, 256>>>(e_dec, Wl_g, Wr_g, n, zBlocks);

    const int gBlocks = (n + 127) / 128;
    k_mma<<<2 * gBlocks, 256, SM_GEMM_TOTAL>>>(x, bl_g, br_g, gBlocks, n);
    k_gemmd<<<(n + 31) / 32, 256>>>(x, Wl_d, Wr_d, bl_d, br_d, n);

    k_edges<<<3 * eBlocks, 256>>>(e0, e1, e_dec, att_d, E, eBlocks);

    k_scan1<<<2 * nb, 512>>>(n, nb);
    k_scan2<<<1, 256>>>(n, nb);
    k_scan3<<<2 * nb, 512>>>(n, nb);

    k_scatter2<<<2 * eBlocks, 256>>>(e0, e1, E, eBlocks);

    k_agg<<<(n + 7) / 8, 256>>>(att_g, bias_g, gum, att_d, bias_d, out, n);
}

// round 8
// speedup vs baseline: 1.6428x; 1.0340x over previous
#include <cuda_runtime.h>
#include <cuda_bf16.h>
#include <cstdint>

#define MAXN 100000
#define MAXE 1600000

// ---------------- device scratch ----------------
__device__ __align__(16) float g_xl[(size_t)MAXN * 128];
__device__ __align__(16) float g_xr[(size_t)MAXN * 128];
__device__ __align__(16) float4 g_xd[MAXN];    // (xl0, xl1, xr0, xr1) decision projections
__device__ __align__(16) float4 g_dacc[MAXN];  // (sum_w, sum_w*xl0, sum_w*xl1, 0)
__device__ int   g_cnt0[MAXN], g_cnt1[MAXN];
__device__ int   g_off0[MAXN + 1], g_off1[MAXN + 1];
__device__ int   g_cur0[MAXN], g_cur1[MAXN];
__device__ int   g_csr0[MAXE], g_csr1[MAXE];
__device__ int   g_part[512];
__device__ int   g_is64;
// W^T bf16 hi/lo, layout [n][k] (k contiguous): [Wl_hi, Wl_lo, Wr_hi, Wr_lo]
__device__ __align__(16) __nv_bfloat16 g_wtb[4][16384];

// ---------------- helpers ----------------
__device__ __forceinline__ float lrelu(float v) { return v > 0.f ? v : 0.2f * v; }

__device__ __forceinline__ float warp_sum(float v) {
#pragma unroll
    for (int o = 16; o; o >>= 1) v += __shfl_xor_sync(0xffffffffu, v, o);
    return v;
}

__device__ __forceinline__ uint32_t smem_u32(const void* p) {
    uint32_t a;
    asm("{ .reg .u64 t; cvta.to.shared.u64 t, %1; cvt.u32.u64 %0, t; }" : "=r"(a) : "l"(p));
    return a;
}

__device__ __forceinline__ void ldsm_x4(uint32_t* r, uint32_t addr) {
    asm volatile("ldmatrix.sync.aligned.m8n8.x4.shared.b16 {%0,%1,%2,%3}, [%4];"
                 : "=r"(r[0]), "=r"(r[1]), "=r"(r[2]), "=r"(r[3]) : "r"(addr));
}
__device__ __forceinline__ void mma16816(float* d, const uint32_t* a, const uint32_t* b) {
    asm volatile(
        "mma.sync.aligned.m16n8k16.row.col.f32.bf16.bf16.f32 "
        "{%0,%1,%2,%3}, {%4,%5,%6,%7}, {%8,%9}, {%0,%1,%2,%3};"
        : "+f"(d[0]), "+f"(d[1]), "+f"(d[2]), "+f"(d[3])
        : "r"(a[0]), "r"(a[1]), "r"(a[2]), "r"(a[3]), "r"(b[0]), "r"(b[1]));
}

// vector fp32 reduction (sm_90+, family-portable PTX)
__device__ __forceinline__ void red4(float4* p, float a, float b, float c) {
    asm volatile("red.global.add.v4.f32 [%0], {%1, %2, %3, %4};"
                 :: "l"(p), "f"(a), "f"(b), "f"(c), "f"(0.f) : "memory");
}

// ---------------- fused setup: zero | prepW | detect | gemmd ----------------
__global__ void k_setup(const int* __restrict__ ed, const float* __restrict__ x,
                        const float* __restrict__ wlg, const float* __restrict__ wrg,
                        const float* __restrict__ wld, const float* __restrict__ wrd,
                        const float* __restrict__ bld, const float* __restrict__ brd,
                        int n, int zBlocks) {
    int b = blockIdx.x;
    if (b < zBlocks) {                     // zero role
        int i = b * 256 + threadIdx.x;
        if (i < n) {
            g_dacc[i] = make_float4(0.f, 0.f, 0.f, 0.f);
            g_cnt0[i] = 0; g_cnt1[i] = 0;
        }
        return;
    }
    if (b < zBlocks + 128) {               // prepW role
        int i = (b - zBlocks) * 256 + threadIdx.x;  // 0..32767
        int m = i >> 14;
        int rem = i & 16383;
        int k = rem >> 7, nn = rem & 127;
        float w = (m ? wrg : wlg)[k * 128 + nn];
        __nv_bfloat16 hi = __float2bfloat16(w);
        __nv_bfloat16 lo = __float2bfloat16(w - __bfloat162float(hi));
        g_wtb[2 * m + 0][nn * 128 + k] = hi;
        g_wtb[2 * m + 1][nn * 128 + k] = lo;
        return;
    }
    if (b == zBlocks + 128) {              // detect role
        if (threadIdx.x < 32) {
            int t = threadIdx.x;
            int nz = ed[2 * t + 1] | ed[2 * (t + 32) + 1] | ed[2 * (t + 64) + 1] |
                     ed[2 * (t + 96) + 1];
            unsigned m = __ballot_sync(0xffffffffu, nz != 0);
            if (t == 0) g_is64 = (m == 0) ? 1 : 0;
        }
        return;
    }
    // gemmd role: 4 nodes/warp, exact fp32
    int warp = ((b - zBlocks - 129) * 256 + threadIdx.x) >> 5;
    int base = warp * 4;
    if (base >= n) return;
    int lane = threadIdx.x & 31;
    const float2* WL = (const float2*)wld;
    const float2* WR = (const float2*)wrd;
    float2 wa[4], wb[4];
#pragma unroll
    for (int j = 0; j < 4; j++) {
        wa[j] = __ldg(&WL[lane * 4 + j]);
        wb[j] = __ldg(&WR[lane * 4 + j]);
    }
    int cnt = n - base; if (cnt > 4) cnt = 4;
    float4 xv[4];
#pragma unroll
    for (int t = 0; t < 4; t++)
        xv[t] = (t < cnt) ? __ldg((const float4*)(x + (size_t)(base + t) * 128) + lane)
                          : make_float4(0.f, 0.f, 0.f, 0.f);
    float pl0[4], pl1[4], pr0[4], pr1[4];
#pragma unroll
    for (int t = 0; t < 4; t++) {
        float xs[4] = {xv[t].x, xv[t].y, xv[t].z, xv[t].w};
        pl0[t] = pl1[t] = pr0[t] = pr1[t] = 0.f;
#pragma unroll
        for (int j = 0; j < 4; j++) {
            pl0[t] += xs[j] * wa[j].x; pl1[t] += xs[j] * wa[j].y;
            pr0[t] += xs[j] * wb[j].x; pr1[t] += xs[j] * wb[j].y;
        }
    }
#pragma unroll
    for (int o = 16; o; o >>= 1) {
#pragma unroll
        for (int t = 0; t < 4; t++) {
            pl0[t] += __shfl_xor_sync(0xffffffffu, pl0[t], o);
            pl1[t] += __shfl_xor_sync(0xffffffffu, pl1[t], o);
            pr0[t] += __shfl_xor_sync(0xffffffffu, pr0[t], o);
            pr1[t] += __shfl_xor_sync(0xffffffffu, pr1[t], o);
        }
    }
    if (lane == 0) {
        float b0 = __ldg(&bld[0]), b1 = __ldg(&bld[1]);
        float c0 = __ldg(&brd[0]), c1 = __ldg(&brd[1]);
#pragma unroll
        for (int t = 0; t < 4; t++)
            if (t < cnt)
                g_xd[base + t] = make_float4(pl0[t] + b0, pl1[t] + b1,
                                             pr0[t] + c0, pr1[t] + c1);
    }
}

// ---------------- bf16 split-K mma.sync GEMM (both outputs, one grid) ----------------
#define SLAB_ROW 72
#define SM_A_HI 0
#define SM_A_LO 18432
#define SM_B_HI 36864
#define SM_B_LO 55296
#define SM_GEMM_TOTAL 73728

__global__ __launch_bounds__(256, 2) void k_mma(const float* __restrict__ X,
                                                const float* __restrict__ bl,
                                                const float* __restrict__ br,
                                                int gBlocks, int n) {
    extern __shared__ __align__(16) unsigned char sm[];
    __nv_bfloat16* Ah = (__nv_bfloat16*)(sm + SM_A_HI);
    __nv_bfloat16* Al = (__nv_bfloat16*)(sm + SM_A_LO);
    __nv_bfloat16* Bh = (__nv_bfloat16*)(sm + SM_B_HI);
    __nv_bfloat16* Bl = (__nv_bfloat16*)(sm + SM_B_LO);

    const int which = (blockIdx.x >= gBlocks) ? 1 : 0;
    const int mBase = (blockIdx.x - which * gBlocks) * 128;
    const int tid = threadIdx.x;
    const int w = tid >> 5;
    const int lane = tid & 31;
    const int wm = w & 3;
    const int wcol = (w >> 2) * 64;

    float acc[2][8][4];
#pragma unroll
    for (int a = 0; a < 2; a++)
#pragma unroll
        for (int b = 0; b < 8; b++)
#pragma unroll
            for (int c = 0; c < 4; c++) acc[a][b][c] = 0.f;

    const __nv_bfloat16* WH = g_wtb[2 * which];
    const __nv_bfloat16* WL = g_wtb[2 * which + 1];

#pragma unroll
    for (int slab = 0; slab < 2; slab++) {
        const int k0 = slab * 64;
#pragma unroll
        for (int it = 0; it < 8; it++) {
            int idx = tid + it * 256;
            int row = idx >> 4;
            int q = idx & 15;
            float4 v = make_float4(0.f, 0.f, 0.f, 0.f);
            int gr = mBase + row;
            if (gr < n) v = __ldg((const float4*)(X + (size_t)gr * 128 + k0) + q);
            __nv_bfloat162 h01 = __floats2bfloat162_rn(v.x, v.y);
            __nv_bfloat162 h23 = __floats2bfloat162_rn(v.z, v.w);
            float2 f01 = __bfloat1622float2(h01);
            float2 f23 = __bfloat1622float2(h23);
            __nv_bfloat162 l01 = __floats2bfloat162_rn(v.x - f01.x, v.y - f01.y);
            __nv_bfloat162 l23 = __floats2bfloat162_rn(v.z - f23.x, v.w - f23.y);
            uint2 hw, lw;
            hw.x = *(uint32_t*)&h01; hw.y = *(uint32_t*)&h23;
            lw.x = *(uint32_t*)&l01; lw.y = *(uint32_t*)&l23;
            *(uint2*)&Ah[row * SLAB_ROW + q * 4] = hw;
            *(uint2*)&Al[row * SLAB_ROW + q * 4] = lw;
        }
#pragma unroll
        for (int it = 0; it < 8; it++) {
            int idx = tid + it * 256;
            int ver = idx >> 10;
            int r = (idx >> 3) & 127;
            int j = idx & 7;
            const float4* src = (const float4*)((ver ? WL : WH) + r * 128 + k0);
            float4 val = __ldg(src + j);
            __nv_bfloat16* dst = (ver ? Bl : Bh) + r * SLAB_ROW + j * 8;
            *(float4*)dst = val;
        }
        __syncthreads();

#pragma unroll
        for (int kb = 0; kb < 4; kb++) {
            uint32_t afh[2][4], afl[2][4];
#pragma unroll
            for (int mb = 0; mb < 2; mb++) {
                int row = wm * 32 + mb * 16 + (lane & 7) + ((lane & 8) ? 8 : 0);
                int colb = kb * 32 + ((lane & 16) ? 16 : 0);
                ldsm_x4(afh[mb], smem_u32(&Ah[row * SLAB_ROW]) + colb);
                ldsm_x4(afl[mb], smem_u32(&Al[row * SLAB_ROW]) + colb);
            }
#pragma unroll
            for (int np = 0; np < 4; np++) {
                int nrow = wcol + np * 16 + ((lane & 16) ? 8 : 0) + (lane & 7);
                int colb = kb * 32 + ((lane & 8) ? 16 : 0);
                uint32_t bh[4], bl[4];
                ldsm_x4(bh, smem_u32(&Bh[nrow * SLAB_ROW]) + colb);
                ldsm_x4(bl, smem_u32(&Bl[nrow * SLAB_ROW]) + colb);
#pragma unroll
                for (int half = 0; half < 2; half++) {
                    int nb = np * 2 + half;
#pragma unroll
                    for (int mb = 0; mb < 2; mb++) {
                        mma16816(acc[mb][nb], afh[mb], bh + 2 * half);
                        mma16816(acc[mb][nb], afh[mb], bl + 2 * half);
                        mma16816(acc[mb][nb], afl[mb], bh + 2 * half);
                    }
                }
            }
        }
        __syncthreads();
    }

    float* dst = which ? g_xr : g_xl;
    const float* bias = which ? br : bl;
    int g = lane >> 2, tg = lane & 3;
#pragma unroll
    for (int mb = 0; mb < 2; mb++) {
#pragma unroll
        for (int nb = 0; nb < 8; nb++) {
            int col = wcol + nb * 8 + 2 * tg;
            float2 bv = __ldg((const float2*)(bias + col));
            int row0 = mBase + wm * 32 + mb * 16 + g;
            if (row0 < n) {
                float2 o = make_float2(acc[mb][nb][0] + bv.x, acc[mb][nb][1] + bv.y);
                *(float2*)(dst + (size_t)row0 * 128 + col) = o;
            }
            int row1 = row0 + 8;
            if (row1 < n) {
                float2 o = make_float2(acc[mb][nb][2] + bv.x, acc[mb][nb][3] + bv.y);
                *(float2*)(dst + (size_t)row1 * 128 + col) = o;
            }
        }
    }
}

// ---------------- fused edge pass: hist(e0) | hist(e1) | decision edges ----------------
__global__ void k_edges(const int* __restrict__ e0, const int* __restrict__ e1,
                        const int* __restrict__ ed, const float* __restrict__ attd,
                        int E, int eBlocks) {
    int role = blockIdx.x / eBlocks;
    int i = (blockIdx.x - role * eBlocks) * blockDim.x + threadIdx.x;
    if (i >= E) return;
    int is64 = g_is64;
    if (role == 0) {
        int d = is64 ? e0[2 * (E + i)] : e0[E + i];
        atomicAdd(&g_cnt0[d], 1);
    } else if (role == 1) {
        int d = is64 ? e1[2 * (E + i)] : e1[E + i];
        atomicAdd(&g_cnt1[d], 1);
    } else {
        int s = is64 ? ed[2 * i] : ed[i];
        int d = is64 ? ed[2 * (E + i)] : ed[E + i];
        float4 vs = __ldg(&g_xd[s]);   // xl0, xl1 in .x, .y
        float4 vd = __ldg(&g_xd[d]);   // xr0, xr1 in .z, .w
        float a0 = __ldg(&attd[0]), a1 = __ldg(&attd[1]);
        float ee = a0 * lrelu(vs.x + vd.z) + a1 * lrelu(vs.y + vd.w);
        float w = expf(fminf(ee, 75.f));
        red4(&g_dacc[d], w, w * vs.x, w * vs.y);
    }
}

// ---------------- scans ----------------
__global__ void k_scan1(int n, int nb) {
    int set = (blockIdx.x >= nb) ? 1 : 0;
    int b = blockIdx.x - set * nb;
    int i = b * 512 + threadIdx.x;
    const int* cnt = set ? g_cnt1 : g_cnt0;
    __shared__ int smem[512];
    smem[threadIdx.x] = (i < n) ? cnt[i] : 0;
    __syncthreads();
    for (int o = 256; o; o >>= 1) {
        if (threadIdx.x < o) smem[threadIdx.x] += smem[threadIdx.x + o];
        __syncthreads();
    }
    if (threadIdx.x == 0) g_part[set * 256 + b] = smem[0];
}

__global__ void k_scan2(int n, int nb) {
    __shared__ int smem[256];
    int t = threadIdx.x;
    for (int set = 0; set < 2; set++) {
        int v = (t < nb) ? g_part[set * 256 + t] : 0;
        smem[t] = v;
        __syncthreads();
        for (int o = 1; o < 256; o <<= 1) {
            int x = (t >= o) ? smem[t - o] : 0;
            __syncthreads();
            smem[t] += x;
            __syncthreads();
        }
        int incl = smem[t];
        if (t < nb) g_part[set * 256 + t] = incl - v;
        if (t == nb - 1) { if (set) g_off1[n] = incl; else g_off0[n] = incl; }
        __syncthreads();
    }
}

__global__ void k_scan3(int n, int nb) {
    int set = (blockIdx.x >= nb) ? 1 : 0;
    int b = blockIdx.x - set * nb;
    int i = b * 512 + threadIdx.x;
    const int* cnt = set ? g_cnt1 : g_cnt0;
    __shared__ int smem[512];
    int t = threadIdx.x;
    int v = (i < n) ? cnt[i] : 0;
    smem[t] = v;
    __syncthreads();
    for (int o = 1; o < 512; o <<= 1) {
        int x = (t >= o) ? smem[t - o] : 0;
        __syncthreads();
        smem[t] += x;
        __syncthreads();
    }
    int excl = smem[t] - v;
    if (i < n) {
        int off = g_part[set * 256 + b] + excl;
        if (set) { g_off1[i] = off; g_cur1[i] = off; }
        else     { g_off0[i] = off; g_cur0[i] = off; }
    }
}

// ---------------- fused scatter ----------------
__global__ void k_scatter2(const int* __restrict__ e0, const int* __restrict__ e1,
                           int E, int eBlocks) {
    int set = (blockIdx.x >= eBlocks) ? 1 : 0;
    int i = (blockIdx.x - set * eBlocks) * blockDim.x + threadIdx.x;
    if (i >= E) return;
    int is64 = g_is64;
    const int* e = set ? e1 : e0;
    int s = is64 ? e[2 * i] : e[i];
    int d = is64 ? e[2 * (E + i)] : e[E + i];
    int p = atomicAdd(set ? &g_cur1[d] : &g_cur0[d], 1);
    if (p >= 0 && p < MAXE) { if (set) g_csr1[p] = s; else g_csr0[p] = s; }
}

// ---------------- gated aggregation (decision folded in, 4-edge pipeline) ----------------
__global__ __launch_bounds__(256) void k_agg(const float* __restrict__ att,
                                             const float* __restrict__ bias,
                                             const float* __restrict__ gum,
                                             const float* __restrict__ attd,
                                             const float* __restrict__ biasd,
                                             float* __restrict__ out, int n) {
    int w = (blockIdx.x * blockDim.x + threadIdx.x) >> 5;
    if (w >= n) return;
    int lane = threadIdx.x & 31;

    int k;
    float g;
    {
        float4 xd = __ldg(&g_xd[w]);        // xl0, xl1, xr0, xr1
        float a0 = __ldg(&attd[0]), a1 = __ldg(&attd[1]);
        float ee = a0 * lrelu(xd.x + xd.z) + a1 * lrelu(xd.y + xd.w);
        float wsl = expf(fminf(ee, 75.f));
        float4 dacc = __ldg(&g_dacc[w]);
        float s = dacc.x + wsl;
        float A0 = dacc.y + wsl * xd.x;
        float A1 = dacc.z + wsl * xd.y;
        float inv = 1.f / (s + 1e-16f);
        float l0 = A0 * inv + __ldg(&biasd[0]);
        float l1 = A1 * inv + __ldg(&biasd[1]);
        float z0 = (l0 + gum[2 * w]) * 2.0f;
        float z1 = (l1 + gum[2 * w + 1]) * 2.0f;
        k = (z0 >= z1) ? 0 : 1;
        float du = (k == 0) ? (z1 - z0) : (z0 - z1);
        float p = 1.f / (1.f + expf(du));
        volatile float t = 1.0f + p;
        g = t - p;
    }

    const int* csr = k ? g_csr1 : g_csr0;
    const int* off = k ? g_off1 : g_off0;
    int beg = off[w], end = off[w + 1];

    float4 a4 = *(const float4*)(att + lane * 4);
    const float4* xlp = (const float4*)g_xl;
    float4 r4 = *((const float4*)(g_xr) + (size_t)w * 32 + lane);

    float4 v = xlp[(size_t)w * 32 + lane];
    float p = a4.x * lrelu(v.x + r4.x) + a4.y * lrelu(v.y + r4.y) +
              a4.z * lrelu(v.z + r4.z) + a4.w * lrelu(v.w + r4.w);
    float e = warp_sum(p);
    float wt = __expf(fminf(e, 75.f));
    float s = wt;
    float4 acc = make_float4(wt * v.x, wt * v.y, wt * v.z, wt * v.w);

    int j = beg;
#pragma unroll 1
    for (; j + 4 <= end; j += 4) {
        int s0 = __ldg(&csr[j]);
        int s1 = __ldg(&csr[j + 1]);
        int s2 = __ldg(&csr[j + 2]);
        int s3 = __ldg(&csr[j + 3]);
        float4 u0 = xlp[(size_t)s0 * 32 + lane];
        float4 u1 = xlp[(size_t)s1 * 32 + lane];
        float4 u2 = xlp[(size_t)s2 * 32 + lane];
        float4 u3 = xlp[(size_t)s3 * 32 + lane];
        float q0 = a4.x * lrelu(u0.x + r4.x) + a4.y * lrelu(u0.y + r4.y) +
                   a4.z * lrelu(u0.z + r4.z) + a4.w * lrelu(u0.w + r4.w);
        float q1 = a4.x * lrelu(u1.x + r4.x) + a4.y * lrelu(u1.y + r4.y) +
                   a4.z * lrelu(u1.z + r4.z) + a4.w * lrelu(u1.w + r4.w);
        float q2 = a4.x * lrelu(u2.x + r4.x) + a4.y * lrelu(u2.y + r4.y) +
                   a4.z * lrelu(u2.z + r4.z) + a4.w * lrelu(u2.w + r4.w);
        float q3 = a4.x * lrelu(u3.x + r4.x) + a4.y * lrelu(u3.y + r4.y) +
                   a4.z * lrelu(u3.z + r4.z) + a4.w * lrelu(u3.w + r4.w);
#pragma unroll
        for (int o = 16; o; o >>= 1) {
            q0 += __shfl_xor_sync(0xffffffffu, q0, o);
            q1 += __shfl_xor_sync(0xffffffffu, q1, o);
            q2 += __shfl_xor_sync(0xffffffffu, q2, o);
            q3 += __shfl_xor_sync(0xffffffffu, q3, o);
        }
        float w0 = __expf(fminf(q0, 75.f));
        float w1 = __expf(fminf(q1, 75.f));
        float w2 = __expf(fminf(q2, 75.f));
        float w3 = __expf(fminf(q3, 75.f));
        s += (w0 + w1) + (w2 + w3);
        acc.x += w0 * u0.x + w1 * u1.x + w2 * u2.x + w3 * u3.x;
        acc.y += w0 * u0.y + w1 * u1.y + w2 * u2.y + w3 * u3.y;
        acc.z += w0 * u0.z + w1 * u1.z + w2 * u2.z + w3 * u3.z;
        acc.w += w0 * u0.w + w1 * u1.w + w2 * u2.w + w3 * u3.w;
    }
#pragma unroll 1
    for (; j < end; j++) {
        int src = __ldg(&csr[j]);
        float4 u = xlp[(size_t)src * 32 + lane];
        float q = a4.x * lrelu(u.x + r4.x) + a4.y * lrelu(u.y + r4.y) +
                  a4.z * lrelu(u.z + r4.z) + a4.w * lrelu(u.w + r4.w);
        float e2 = warp_sum(q);
        float w2 = __expf(fminf(e2, 75.f));
        s += w2;
        acc.x += w2 * u.x; acc.y += w2 * u.y; acc.z += w2 * u.z; acc.w += w2 * u.w;
    }

    float inv = g / (s + 1e-16f);
    float4 b4 = *(const float4*)(bias + lane * 4);
    float4 o4 = make_float4(acc.x * inv + b4.x * g, acc.y * inv + b4.y * g,
                            acc.z * inv + b4.z * g, acc.w * inv + b4.w * g);
    *((float4*)out + (size_t)w * 32 + lane) = o4;
}

// ---------------- launcher ----------------
extern "C" void kernel_launch(void* const* d_in, const int* in_sizes, int n_in,
                              void* d_out, int out_size) {
    const float* x      = (const float*)d_in[0];
    const int*   e_dec  = (const int*)d_in[1];
    const int*   e0     = (const int*)d_in[2];
    const int*   e1     = (const int*)d_in[3];
    const float* gum    = (const float*)d_in[4];
    const float* Wl_g   = (const float*)d_in[5];
    const float* Wr_g   = (const float*)d_in[6];
    const float* bl_g   = (const float*)d_in[7];
    const float* br_g   = (const float*)d_in[8];
    const float* att_g  = (const float*)d_in[9];
    const float* bias_g = (const float*)d_in[10];
    const float* Wl_d   = (const float*)d_in[11];
    const float* Wr_d   = (const float*)d_in[12];
    const float* bl_d   = (const float*)d_in[13];
    const float* br_d   = (const float*)d_in[14];
    const float* att_d  = (const float*)d_in[15];
    const float* bias_d = (const float*)d_in[16];
    float* out = (float*)d_out;

    const int n = in_sizes[0] / 128;
    const int E = in_sizes[1] / 2;
    const int nb = (n + 511) / 512;
    const int eBlocks = (E + 255) / 256;
    const int zBlocks = (n + 255) / 256;
    const int dBlocks = (n + 31) / 32;   // gemmd role blocks

    cudaFuncSetAttribute(k_mma, cudaFuncAttributeMaxDynamicSharedMemorySize, SM_GEMM_TOTAL);

    k_setup<<<zBlocks + 128 + 1 + dBlocks, 256>>>(e_dec, x, Wl_g, Wr_g,
                                                  Wl_d, Wr_d, bl_d, br_d, n, zBlocks);

    const int gBlocks = (n + 127) / 128;
    k_mma<<<2 * gBlocks, 256, SM_GEMM_TOTAL>>>(x, bl_g, br_g, gBlocks, n);

    k_edges<<<3 * eBlocks, 256>>>(e0, e1, e_dec, att_d, E, eBlocks);

    k_scan1<<<2 * nb, 512>>>(n, nb);
    k_scan2<<<1, 256>>>(n, nb);
    k_scan3<<<2 * nb, 512>>>(n, nb);

    k_scatter2<<<2 * eBlocks, 256>>>(e0, e1, E, eBlocks);

    k_agg<<<(n + 7) / 8, 256>>>(att_g, bias_g, gum, att_d, bias_d, out, n);
}

// round 9
// speedup vs baseline: 1.7049x; 1.0378x over previous
#include <cuda_runtime.h>
#include <cuda_bf16.h>
#include <cstdint>

#define MAXN 100000
#define MAXE 1600000

// ---------------- device scratch ----------------
__device__ __align__(16) float g_xl[(size_t)MAXN * 128];
__device__ __align__(16) float g_xr[(size_t)MAXN * 128];
__device__ __align__(16) float4 g_xd[MAXN];    // (xl0, xl1, xr0, xr1) decision projections
__device__ __align__(16) float4 g_dacc[MAXN];  // (sum_w, sum_w*xl0, sum_w*xl1, 0)
__device__ int   g_cnt0[MAXN], g_cnt1[MAXN];
__device__ int   g_off0[MAXN + 1], g_off1[MAXN + 1];
__device__ int   g_cur0[MAXN], g_cur1[MAXN];
__device__ int   g_csr0[MAXE], g_csr1[MAXE];
__device__ int   g_part[512];
__device__ int   g_is64;
// W^T bf16 hi/lo, layout [n][k] (k contiguous): [Wl_hi, Wl_lo, Wr_hi, Wr_lo]
__device__ __align__(16) __nv_bfloat16 g_wtb[4][16384];

// ---------------- helpers ----------------
__device__ __forceinline__ float lrelu(float v) { return v > 0.f ? v : 0.2f * v; }

__device__ __forceinline__ float warp_sum(float v) {
#pragma unroll
    for (int o = 16; o; o >>= 1) v += __shfl_xor_sync(0xffffffffu, v, o);
    return v;
}

__device__ __forceinline__ uint32_t smem_u32(const void* p) {
    uint32_t a;
    asm("{ .reg .u64 t; cvta.to.shared.u64 t, %1; cvt.u32.u64 %0, t; }" : "=r"(a) : "l"(p));
    return a;
}

__device__ __forceinline__ void ldsm_x4(uint32_t* r, uint32_t addr) {
    asm volatile("ldmatrix.sync.aligned.m8n8.x4.shared.b16 {%0,%1,%2,%3}, [%4];"
                 : "=r"(r[0]), "=r"(r[1]), "=r"(r[2]), "=r"(r[3]) : "r"(addr));
}
__device__ __forceinline__ void mma16816(float* d, const uint32_t* a, const uint32_t* b) {
    asm volatile(
        "mma.sync.aligned.m16n8k16.row.col.f32.bf16.bf16.f32 "
        "{%0,%1,%2,%3}, {%4,%5,%6,%7}, {%8,%9}, {%0,%1,%2,%3};"
        : "+f"(d[0]), "+f"(d[1]), "+f"(d[2]), "+f"(d[3])
        : "r"(a[0]), "r"(a[1]), "r"(a[2]), "r"(a[3]), "r"(b[0]), "r"(b[1]));
}

// vector fp32 reduction (sm_90+, family-portable PTX)
__device__ __forceinline__ void red4(float4* p, float a, float b, float c) {
    asm volatile("red.global.add.v4.f32 [%0], {%1, %2, %3, %4};"
                 :: "l"(p), "f"(a), "f"(b), "f"(c), "f"(0.f) : "memory");
}

// ---------------- fused setup: zero | prepW | detect | gemmd ----------------
__global__ void k_setup(const int* __restrict__ ed, const float* __restrict__ x,
                        const float* __restrict__ wlg, const float* __restrict__ wrg,
                        const float* __restrict__ wld, const float* __restrict__ wrd,
                        const float* __restrict__ bld, const float* __restrict__ brd,
                        int n, int zBlocks) {
    int b = blockIdx.x;
    if (b < zBlocks) {                     // zero role
        int i = b * 256 + threadIdx.x;
        if (i < n) {
            g_dacc[i] = make_float4(0.f, 0.f, 0.f, 0.f);
            g_cnt0[i] = 0; g_cnt1[i] = 0;
        }
        return;
    }
    if (b < zBlocks + 128) {               // prepW role
        int i = (b - zBlocks) * 256 + threadIdx.x;  // 0..32767
        int m = i >> 14;
        int rem = i & 16383;
        int k = rem >> 7, nn = rem & 127;
        float w = (m ? wrg : wlg)[k * 128 + nn];
        __nv_bfloat16 hi = __float2bfloat16(w);
        __nv_bfloat16 lo = __float2bfloat16(w - __bfloat162float(hi));
        g_wtb[2 * m + 0][nn * 128 + k] = hi;
        g_wtb[2 * m + 1][nn * 128 + k] = lo;
        return;
    }
    if (b == zBlocks + 128) {              // detect role
        if (threadIdx.x < 32) {
            int t = threadIdx.x;
            int nz = ed[2 * t + 1] | ed[2 * (t + 32) + 1] | ed[2 * (t + 64) + 1] |
                     ed[2 * (t + 96) + 1];
            unsigned m = __ballot_sync(0xffffffffu, nz != 0);
            if (t == 0) g_is64 = (m == 0) ? 1 : 0;
        }
        return;
    }
    // gemmd role: 4 nodes/warp, exact fp32
    int warp = ((b - zBlocks - 129) * 256 + threadIdx.x) >> 5;
    int base = warp * 4;
    if (base >= n) return;
    int lane = threadIdx.x & 31;
    const float2* WL = (const float2*)wld;
    const float2* WR = (const float2*)wrd;
    float2 wa[4], wb[4];
#pragma unroll
    for (int j = 0; j < 4; j++) {
        wa[j] = __ldg(&WL[lane * 4 + j]);
        wb[j] = __ldg(&WR[lane * 4 + j]);
    }
    int cnt = n - base; if (cnt > 4) cnt = 4;
    float4 xv[4];
#pragma unroll
    for (int t = 0; t < 4; t++)
        xv[t] = (t < cnt) ? __ldg((const float4*)(x + (size_t)(base + t) * 128) + lane)
                          : make_float4(0.f, 0.f, 0.f, 0.f);
    float pl0[4], pl1[4], pr0[4], pr1[4];
#pragma unroll
    for (int t = 0; t < 4; t++) {
        float xs[4] = {xv[t].x, xv[t].y, xv[t].z, xv[t].w};
        pl0[t] = pl1[t] = pr0[t] = pr1[t] = 0.f;
#pragma unroll
        for (int j = 0; j < 4; j++) {
            pl0[t] += xs[j] * wa[j].x; pl1[t] += xs[j] * wa[j].y;
            pr0[t] += xs[j] * wb[j].x; pr1[t] += xs[j] * wb[j].y;
        }
    }
#pragma unroll
    for (int o = 16; o; o >>= 1) {
#pragma unroll
        for (int t = 0; t < 4; t++) {
            pl0[t] += __shfl_xor_sync(0xffffffffu, pl0[t], o);
            pl1[t] += __shfl_xor_sync(0xffffffffu, pl1[t], o);
            pr0[t] += __shfl_xor_sync(0xffffffffu, pr0[t], o);
            pr1[t] += __shfl_xor_sync(0xffffffffu, pr1[t], o);
        }
    }
    if (lane == 0) {
        float b0 = __ldg(&bld[0]), b1 = __ldg(&bld[1]);
        float c0 = __ldg(&brd[0]), c1 = __ldg(&brd[1]);
#pragma unroll
        for (int t = 0; t < 4; t++)
            if (t < cnt)
                g_xd[base + t] = make_float4(pl0[t] + b0, pl1[t] + b1,
                                             pr0[t] + c0, pr1[t] + c1);
    }
}

// ---------------- bf16 split-K mma.sync GEMM (both outputs, one grid) ----------------
#define SLAB_ROW 72
#define SM_A_HI 0
#define SM_A_LO 18432
#define SM_B_HI 36864
#define SM_B_LO 55296
#define SM_GEMM_TOTAL 73728

__global__ __launch_bounds__(256, 2) void k_mma(const float* __restrict__ X,
                                                const float* __restrict__ bl,
                                                const float* __restrict__ br,
                                                int gBlocks, int n) {
    extern __shared__ __align__(16) unsigned char sm[];
    __nv_bfloat16* Ah = (__nv_bfloat16*)(sm + SM_A_HI);
    __nv_bfloat16* Al = (__nv_bfloat16*)(sm + SM_A_LO);
    __nv_bfloat16* Bh = (__nv_bfloat16*)(sm + SM_B_HI);
    __nv_bfloat16* Bl = (__nv_bfloat16*)(sm + SM_B_LO);

    const int which = (blockIdx.x >= gBlocks) ? 1 : 0;
    const int mBase = (blockIdx.x - which * gBlocks) * 128;
    const int tid = threadIdx.x;
    const int w = tid >> 5;
    const int lane = tid & 31;
    const int wm = w & 3;
    const int wcol = (w >> 2) * 64;

    float acc[2][8][4];
#pragma unroll
    for (int a = 0; a < 2; a++)
#pragma unroll
        for (int b = 0; b < 8; b++)
#pragma unroll
            for (int c = 0; c < 4; c++) acc[a][b][c] = 0.f;

    const __nv_bfloat16* WH = g_wtb[2 * which];
    const __nv_bfloat16* WL = g_wtb[2 * which + 1];

#pragma unroll
    for (int slab = 0; slab < 2; slab++) {
        const int k0 = slab * 64;
#pragma unroll
        for (int it = 0; it < 8; it++) {
            int idx = tid + it * 256;
            int row = idx >> 4;
            int q = idx & 15;
            float4 v = make_float4(0.f, 0.f, 0.f, 0.f);
            int gr = mBase + row;
            if (gr < n) v = __ldg((const float4*)(X + (size_t)gr * 128 + k0) + q);
            __nv_bfloat162 h01 = __floats2bfloat162_rn(v.x, v.y);
            __nv_bfloat162 h23 = __floats2bfloat162_rn(v.z, v.w);
            float2 f01 = __bfloat1622float2(h01);
            float2 f23 = __bfloat1622float2(h23);
            __nv_bfloat162 l01 = __floats2bfloat162_rn(v.x - f01.x, v.y - f01.y);
            __nv_bfloat162 l23 = __floats2bfloat162_rn(v.z - f23.x, v.w - f23.y);
            uint2 hw, lw;
            hw.x = *(uint32_t*)&h01; hw.y = *(uint32_t*)&h23;
            lw.x = *(uint32_t*)&l01; lw.y = *(uint32_t*)&l23;
            *(uint2*)&Ah[row * SLAB_ROW + q * 4] = hw;
            *(uint2*)&Al[row * SLAB_ROW + q * 4] = lw;
        }
#pragma unroll
        for (int it = 0; it < 8; it++) {
            int idx = tid + it * 256;
            int ver = idx >> 10;
            int r = (idx >> 3) & 127;
            int j = idx & 7;
            const float4* src = (const float4*)((ver ? WL : WH) + r * 128 + k0);
            float4 val = __ldg(src + j);
            __nv_bfloat16* dst = (ver ? Bl : Bh) + r * SLAB_ROW + j * 8;
            *(float4*)dst = val;
        }
        __syncthreads();

#pragma unroll
        for (int kb = 0; kb < 4; kb++) {
            uint32_t afh[2][4], afl[2][4];
#pragma unroll
            for (int mb = 0; mb < 2; mb++) {
                int row = wm * 32 + mb * 16 + (lane & 7) + ((lane & 8) ? 8 : 0);
                int colb = kb * 32 + ((lane & 16) ? 16 : 0);
                ldsm_x4(afh[mb], smem_u32(&Ah[row * SLAB_ROW]) + colb);
                ldsm_x4(afl[mb], smem_u32(&Al[row * SLAB_ROW]) + colb);
            }
#pragma unroll
            for (int np = 0; np < 4; np++) {
                int nrow = wcol + np * 16 + ((lane & 16) ? 8 : 0) + (lane & 7);
                int colb = kb * 32 + ((lane & 8) ? 16 : 0);
                uint32_t bh[4], bl[4];
                ldsm_x4(bh, smem_u32(&Bh[nrow * SLAB_ROW]) + colb);
                ldsm_x4(bl, smem_u32(&Bl[nrow * SLAB_ROW]) + colb);
#pragma unroll
                for (int half = 0; half < 2; half++) {
                    int nb = np * 2 + half;
#pragma unroll
                    for (int mb = 0; mb < 2; mb++) {
                        mma16816(acc[mb][nb], afh[mb], bh + 2 * half);
                        mma16816(acc[mb][nb], afh[mb], bl + 2 * half);
                        mma16816(acc[mb][nb], afl[mb], bh + 2 * half);
                    }
                }
            }
        }
        __syncthreads();
    }

    float* dst = which ? g_xr : g_xl;
    const float* bias = which ? br : bl;
    int g = lane >> 2, tg = lane & 3;
#pragma unroll
    for (int mb = 0; mb < 2; mb++) {
#pragma unroll
        for (int nb = 0; nb < 8; nb++) {
            int col = wcol + nb * 8 + 2 * tg;
            float2 bv = __ldg((const float2*)(bias + col));
            int row0 = mBase + wm * 32 + mb * 16 + g;
            if (row0 < n) {
                float2 o = make_float2(acc[mb][nb][0] + bv.x, acc[mb][nb][1] + bv.y);
                *(float2*)(dst + (size_t)row0 * 128 + col) = o;
            }
            int row1 = row0 + 8;
            if (row1 < n) {
                float2 o = make_float2(acc[mb][nb][2] + bv.x, acc[mb][nb][3] + bv.y);
                *(float2*)(dst + (size_t)row1 * 128 + col) = o;
            }
        }
    }
}

// ---------------- fused edge pass: hist(e0) | hist(e1) | decision edges ----------------
__global__ void k_edges(const int* __restrict__ e0, const int* __restrict__ e1,
                        const int* __restrict__ ed, const float* __restrict__ attd,
                        int E, int eBlocks) {
    int role = blockIdx.x / eBlocks;
    int i = (blockIdx.x - role * eBlocks) * blockDim.x + threadIdx.x;
    if (i >= E) return;
    int is64 = g_is64;
    if (role == 0) {
        int d = is64 ? e0[2 * (E + i)] : e0[E + i];
        atomicAdd(&g_cnt0[d], 1);
    } else if (role == 1) {
        int d = is64 ? e1[2 * (E + i)] : e1[E + i];
        atomicAdd(&g_cnt1[d], 1);
    } else {
        int s = is64 ? ed[2 * i] : ed[i];
        int d = is64 ? ed[2 * (E + i)] : ed[E + i];
        float4 vs = __ldg(&g_xd[s]);
        float4 vd = __ldg(&g_xd[d]);
        float a0 = __ldg(&attd[0]), a1 = __ldg(&attd[1]);
        float ee = a0 * lrelu(vs.x + vd.z) + a1 * lrelu(vs.y + vd.w);
        float w = expf(fminf(ee, 75.f));
        red4(&g_dacc[d], w, w * vs.x, w * vs.y);
    }
}

// ---------------- scans ----------------
__global__ void k_scan1(int n, int nb) {
    int set = (blockIdx.x >= nb) ? 1 : 0;
    int b = blockIdx.x - set * nb;
    int i = b * 512 + threadIdx.x;
    const int* cnt = set ? g_cnt1 : g_cnt0;
    __shared__ int smem[512];
    smem[threadIdx.x] = (i < n) ? cnt[i] : 0;
    __syncthreads();
    for (int o = 256; o; o >>= 1) {
        if (threadIdx.x < o) smem[threadIdx.x] += smem[threadIdx.x + o];
        __syncthreads();
    }
    if (threadIdx.x == 0) g_part[set * 256 + b] = smem[0];
}

__global__ void k_scan2(int n, int nb) {
    __shared__ int smem[256];
    int t = threadIdx.x;
    for (int set = 0; set < 2; set++) {
        int v = (t < nb) ? g_part[set * 256 + t] : 0;
        smem[t] = v;
        __syncthreads();
        for (int o = 1; o < 256; o <<= 1) {
            int x = (t >= o) ? smem[t - o] : 0;
            __syncthreads();
            smem[t] += x;
            __syncthreads();
        }
        int incl = smem[t];
        if (t < nb) g_part[set * 256 + t] = incl - v;
        if (t == nb - 1) { if (set) g_off1[n] = incl; else g_off0[n] = incl; }
        __syncthreads();
    }
}

__global__ void k_scan3(int n, int nb) {
    int set = (blockIdx.x >= nb) ? 1 : 0;
    int b = blockIdx.x - set * nb;
    int i = b * 512 + threadIdx.x;
    const int* cnt = set ? g_cnt1 : g_cnt0;
    __shared__ int smem[512];
    int t = threadIdx.x;
    int v = (i < n) ? cnt[i] : 0;
    smem[t] = v;
    __syncthreads();
    for (int o = 1; o < 512; o <<= 1) {
        int x = (t >= o) ? smem[t - o] : 0;
        __syncthreads();
        smem[t] += x;
        __syncthreads();
    }
    int excl = smem[t] - v;
    if (i < n) {
        int off = g_part[set * 256 + b] + excl;
        if (set) { g_off1[i] = off; g_cur1[i] = off; }
        else     { g_off0[i] = off; g_cur0[i] = off; }
    }
}

// ---------------- fused scatter ----------------
__global__ void k_scatter2(const int* __restrict__ e0, const int* __restrict__ e1,
                           int E, int eBlocks) {
    int set = (blockIdx.x >= eBlocks) ? 1 : 0;
    int i = (blockIdx.x - set * eBlocks) * blockDim.x + threadIdx.x;
    if (i >= E) return;
    int is64 = g_is64;
    const int* e = set ? e1 : e0;
    int s = is64 ? e[2 * i] : e[i];
    int d = is64 ? e[2 * (E + i)] : e[E + i];
    int p = atomicAdd(set ? &g_cur1[d] : &g_cur0[d], 1);
    if (p >= 0 && p < MAXE) { if (set) g_csr1[p] = s; else g_csr0[p] = s; }
}

// ---------------- gated aggregation (decision folded in, 4-edge pipeline) ----------------
__global__ __launch_bounds__(256) void k_agg(const float* __restrict__ att,
                                             const float* __restrict__ bias,
                                             const float* __restrict__ gum,
                                             const float* __restrict__ attd,
                                             const float* __restrict__ biasd,
                                             float* __restrict__ out, int n) {
    int w = (blockIdx.x * blockDim.x + threadIdx.x) >> 5;
    if (w >= n) return;
    int lane = threadIdx.x & 31;

    int k;
    float g;
    {
        float4 xd = __ldg(&g_xd[w]);
        float a0 = __ldg(&attd[0]), a1 = __ldg(&attd[1]);
        float ee = a0 * lrelu(xd.x + xd.z) + a1 * lrelu(xd.y + xd.w);
        float wsl = expf(fminf(ee, 75.f));
        float4 dacc = __ldg(&g_dacc[w]);
        float s = dacc.x + wsl;
        float A0 = dacc.y + wsl * xd.x;
        float A1 = dacc.z + wsl * xd.y;
        float inv = 1.f / (s + 1e-16f);
        float l0 = A0 * inv + __ldg(&biasd[0]);
        float l1 = A1 * inv + __ldg(&biasd[1]);
        float z0 = (l0 + gum[2 * w]) * 2.0f;
        float z1 = (l1 + gum[2 * w + 1]) * 2.0f;
        k = (z0 >= z1) ? 0 : 1;
        float du = (k == 0) ? (z1 - z0) : (z0 - z1);
        float p = 1.f / (1.f + expf(du));
        volatile float t = 1.0f + p;
        g = t - p;
    }

    const int* csr = k ? g_csr1 : g_csr0;
    const int* off = k ? g_off1 : g_off0;
    int beg = off[w], end = off[w + 1];

    float4 a4 = *(const float4*)(att + lane * 4);
    const float4* xlp = (const float4*)g_xl;
    float4 r4 = *((const float4*)(g_xr) + (size_t)w * 32 + lane);

    float4 v = xlp[(size_t)w * 32 + lane];
    float p = a4.x * lrelu(v.x + r4.x) + a4.y * lrelu(v.y + r4.y) +
              a4.z * lrelu(v.z + r4.z) + a4.w * lrelu(v.w + r4.w);
    float e = warp_sum(p);
    float wt = __expf(fminf(e, 75.f));
    float s = wt;
    float4 acc = make_float4(wt * v.x, wt * v.y, wt * v.z, wt * v.w);

    int j = beg;
#pragma unroll 1
    for (; j + 4 <= end; j += 4) {
        int s0 = __ldg(&csr[j]);
        int s1 = __ldg(&csr[j + 1]);
        int s2 = __ldg(&csr[j + 2]);
        int s3 = __ldg(&csr[j + 3]);
        float4 u0 = xlp[(size_t)s0 * 32 + lane];
        float4 u1 = xlp[(size_t)s1 * 32 + lane];
        float4 u2 = xlp[(size_t)s2 * 32 + lane];
        float4 u3 = xlp[(size_t)s3 * 32 + lane];
        float q0 = a4.x * lrelu(u0.x + r4.x) + a4.y * lrelu(u0.y + r4.y) +
                   a4.z * lrelu(u0.z + r4.z) + a4.w * lrelu(u0.w + r4.w);
        float q1 = a4.x * lrelu(u1.x + r4.x) + a4.y * lrelu(u1.y + r4.y) +
                   a4.z * lrelu(u1.z + r4.z) + a4.w * lrelu(u1.w + r4.w);
        float q2 = a4.x * lrelu(u2.x + r4.x) + a4.y * lrelu(u2.y + r4.y) +
                   a4.z * lrelu(u2.z + r4.z) + a4.w * lrelu(u2.w + r4.w);
        float q3 = a4.x * lrelu(u3.x + r4.x) + a4.y * lrelu(u3.y + r4.y) +
                   a4.z * lrelu(u3.z + r4.z) + a4.w * lrelu(u3.w + r4.w);
#pragma unroll
        for (int o = 16; o; o >>= 1) {
            q0 += __shfl_xor_sync(0xffffffffu, q0, o);
            q1 += __shfl_xor_sync(0xffffffffu, q1, o);
            q2 += __shfl_xor_sync(0xffffffffu, q2, o);
            q3 += __shfl_xor_sync(0xffffffffu, q3, o);
        }
        float w0 = __expf(fminf(q0, 75.f));
        float w1 = __expf(fminf(q1, 75.f));
        float w2 = __expf(fminf(q2, 75.f));
        float w3 = __expf(fminf(q3, 75.f));
        s += (w0 + w1) + (w2 + w3);
        acc.x += w0 * u0.x + w1 * u1.x + w2 * u2.x + w3 * u3.x;
        acc.y += w0 * u0.y + w1 * u1.y + w2 * u2.y + w3 * u3.y;
        acc.z += w0 * u0.z + w1 * u1.z + w2 * u2.z + w3 * u3.z;
        acc.w += w0 * u0.w + w1 * u1.w + w2 * u2.w + w3 * u3.w;
    }
#pragma unroll 1
    for (; j < end; j++) {
        int src = __ldg(&csr[j]);
        float4 u = xlp[(size_t)src * 32 + lane];
        float q = a4.x * lrelu(u.x + r4.x) + a4.y * lrelu(u.y + r4.y) +
                  a4.z * lrelu(u.z + r4.z) + a4.w * lrelu(u.w + r4.w);
        float e2 = warp_sum(q);
        float w2 = __expf(fminf(e2, 75.f));
        s += w2;
        acc.x += w2 * u.x; acc.y += w2 * u.y; acc.z += w2 * u.z; acc.w += w2 * u.w;
    }

    float inv = g / (s + 1e-16f);
    float4 b4 = *(const float4*)(bias + lane * 4);
    float4 o4 = make_float4(acc.x * inv + b4.x * g, acc.y * inv + b4.y * g,
                            acc.z * inv + b4.z * g, acc.w * inv + b4.w * g);
    *((float4*)out + (size_t)w * 32 + lane) = o4;
}

// ---------------- launcher (fork/join: k_mma overlaps edge pipeline) ----------------
extern "C" void kernel_launch(void* const* d_in, const int* in_sizes, int n_in,
                              void* d_out, int out_size) {
    const float* x      = (const float*)d_in[0];
    const int*   e_dec  = (const int*)d_in[1];
    const int*   e0     = (const int*)d_in[2];
    const int*   e1     = (const int*)d_in[3];
    const float* gum    = (const float*)d_in[4];
    const float* Wl_g   = (const float*)d_in[5];
    const float* Wr_g   = (const float*)d_in[6];
    const float* bl_g   = (const float*)d_in[7];
    const float* br_g   = (const float*)d_in[8];
    const float* att_g  = (const float*)d_in[9];
    const float* bias_g = (const float*)d_in[10];
    const float* Wl_d   = (const float*)d_in[11];
    const float* Wr_d   = (const float*)d_in[12];
    const float* bl_d   = (const float*)d_in[13];
    const float* br_d   = (const float*)d_in[14];
    const float* att_d  = (const float*)d_in[15];
    const float* bias_d = (const float*)d_in[16];
    float* out = (float*)d_out;

    const int n = in_sizes[0] / 128;
    const int E = in_sizes[1] / 2;
    const int nb = (n + 511) / 512;
    const int eBlocks = (E + 255) / 256;
    const int zBlocks = (n + 255) / 256;
    const int dBlocks = (n + 31) / 32;

    static cudaStream_t s1 = nullptr;
    static cudaEvent_t evFork = nullptr, evJoin = nullptr;
    if (s1 == nullptr) {
        cudaStreamCreateWithFlags(&s1, cudaStreamNonBlocking);
        cudaEventCreateWithFlags(&evFork, cudaEventDisableTiming);
        cudaEventCreateWithFlags(&evJoin, cudaEventDisableTiming);
        cudaFuncSetAttribute(k_mma, cudaFuncAttributeMaxDynamicSharedMemorySize,
                             SM_GEMM_TOTAL);
    }

    // main stream: setup
    k_setup<<<zBlocks + 128 + 1 + dBlocks, 256>>>(e_dec, x, Wl_g, Wr_g,
                                                  Wl_d, Wr_d, bl_d, br_d, n, zBlocks);
    cudaEventRecord(evFork, 0);

    // side stream: GEMM (independent of edge pipeline)
    cudaStreamWaitEvent(s1, evFork, 0);
    const int gBlocks = (n + 127) / 128;
    k_mma<<<2 * gBlocks, 256, SM_GEMM_TOTAL, s1>>>(x, bl_g, br_g, gBlocks, n);
    cudaEventRecord(evJoin, s1);

    // main stream: edge pipeline
    k_edges<<<3 * eBlocks, 256>>>(e0, e1, e_dec, att_d, E, eBlocks);
    k_scan1<<<2 * nb, 512>>>(n, nb);
    k_scan2<<<1, 256>>>(n, nb);
    k_scan3<<<2 * nb, 512>>>(n, nb);
    k_scatter2<<<2 * eBlocks, 256>>>(e0, e1, E, eBlocks);

    // join, then aggregate
    cudaStreamWaitEvent(0, evJoin, 0);
    k_agg<<<(n + 7) / 8, 256>>>(att_g, bias_g, gum, att_d, bias_d, out, n);
}